// round 12
// baseline (speedup 1.0000x reference)
#include <cuda_runtime.h>
#include <cuda_bf16.h>
#include <cstdint>

#define NN 20000
#define MPAD 20096              // NN rounded up to 128
#define NE 320000
#define NT (NE + NN)

// ---------------- scratch (device globals; no allocations allowed) ----------
__device__ float g_xl[(size_t)NN * 1024];
__device__ float g_skip[(size_t)NN * 1024];
__device__ float g_agg[(size_t)NN * 1024];
__device__ uint32_t g_ah[(size_t)MPAD * 512];   // packed bf16-hi A plane [row][k-pair]
__device__ uint32_t g_al[(size_t)MPAD * 512];   // packed bf16-lo A plane
__device__ uint32_t g_bh[(size_t)2048 * 512];   // packed bf16-hi B plane [n][k-pair]
__device__ uint32_t g_bl[(size_t)2048 * 512];   // packed bf16-lo B plane
__device__ float g_asrc[NN * 6];
__device__ float g_adst[NN * 6];
__device__ float g_walpha[(size_t)NT * 6];      // unnormalized softmax weights (CSR order)
__device__ float g_adenom[NN * 6];
__device__ int   g_deg[NN];
__device__ int   g_row[NN + 1];
__device__ int   g_cursor[NN];
__device__ int   g_esrc[NT];
__device__ int   g_edst[NT];
__device__ int   g_csr_src[NT];
__device__ int   g_is64;

// ---------------- edge dtype detection --------------------------------------
__global__ void detect_dtype_kernel(const int* __restrict__ w) {
    if (threadIdx.x == 0) {
        int nz = 0;
        for (int i = 1; i < 2048; i += 2) nz += (w[i] != 0);
        g_is64 = (nz == 0) ? 1 : 0;
    }
}

// ---------------- graph construction ----------------------------------------
__global__ void zero_deg_kernel() {
    int i = blockIdx.x * blockDim.x + threadIdx.x;
    if (i < NN) g_deg[i] = 0;
}

__global__ void build_edges_kernel(const void* __restrict__ ei) {
    int t = blockIdx.x * blockDim.x + threadIdx.x;
    if (t >= NT) return;
    int s, d;
    if (t < NE) {
        if (g_is64) {
            const long long* p = (const long long*)ei;
            s = (int)p[t];
            d = (int)p[NE + t];
        } else {
            const int* p = (const int*)ei;
            s = p[t];
            d = p[NE + t];
        }
        s = min(max(s, 0), NN - 1);
        d = min(max(d, 0), NN - 1);
    } else {
        s = d = t - NE;  // self loop
    }
    g_esrc[t] = s;
    g_edst[t] = d;
    atomicAdd(&g_deg[d], 1);
}

// warp-shuffle hierarchical scan (3 syncs per 1024-chunk)
__global__ void scan_kernel() {
    __shared__ int wsum[32];
    __shared__ int carry;
    int tid = threadIdx.x, lane = tid & 31, wid = tid >> 5;
    if (tid == 0) { carry = 0; g_row[0] = 0; }
    __syncthreads();
    for (int base = 0; base < NN; base += 1024) {
        int i = base + tid;
        int v = (i < NN) ? g_deg[i] : 0;
        int val = v;
#pragma unroll
        for (int off = 1; off < 32; off <<= 1) {
            int t = __shfl_up_sync(0xffffffffu, val, off);
            if (lane >= off) val += t;
        }
        if (lane == 31) wsum[wid] = val;
        __syncthreads();
        if (wid == 0) {
            int s = wsum[lane];
#pragma unroll
            for (int off = 1; off < 32; off <<= 1) {
                int t = __shfl_up_sync(0xffffffffu, s, off);
                if (lane >= off) s += t;
            }
            wsum[lane] = s;
        }
        __syncthreads();
        int prefix = carry + (wid > 0 ? wsum[wid - 1] : 0);
        int incl = prefix + val;
        if (i < NN) {
            g_row[i + 1] = incl;
            g_cursor[i]  = incl - v;
        }
        __syncthreads();
        if (tid == 0) carry += wsum[31];
        __syncthreads();
    }
}

__global__ void scatter_kernel() {
    int t = blockIdx.x * blockDim.x + threadIdx.x;
    if (t >= NT) return;
    int d = g_edst[t];
    int pos = atomicAdd(&g_cursor[d], 1);
    g_csr_src[pos] = g_esrc[t];
}

// ============================================================================
// hi/lo bf16 pre-conversion
// ============================================================================
__device__ __forceinline__ void packpair(float x0, float x1,
                                         uint32_t& hw, uint32_t& lw) {
    uint32_t b0 = __float_as_uint(x0), b1 = __float_as_uint(x1);
    uint32_t h0 = b0 & 0xFFFF0000u, h1 = b1 & 0xFFFF0000u;
    float l0 = x0 - __uint_as_float(h0);
    float l1 = x1 - __uint_as_float(h1);
    __nv_bfloat16 lb0 = __float2bfloat16(l0);
    __nv_bfloat16 lb1 = __float2bfloat16(l1);
    uint16_t u0 = *reinterpret_cast<uint16_t*>(&lb0);
    uint16_t u1 = *reinterpret_cast<uint16_t*>(&lb1);
    hw = (h0 >> 16) | h1;
    lw = (uint32_t)u0 | ((uint32_t)u1 << 16);
}

// A[M,K] fp32 -> packed word planes g_ah/g_al [MPAD][aStride]; zero pad.
__global__ void cvt_a_kernel(const float* __restrict__ A, int M, int K,
                             int aStride) {
    int t = blockIdx.x * blockDim.x + threadIdx.x;
    if (t >= MPAD * aStride) return;
    int row = t / aStride, kp = t - row * aStride;
    float x0 = 0.f, x1 = 0.f;
    if (row < M) {
        int k0 = kp * 2;
        const float* ap = &A[(size_t)row * K];
        if (k0 < K)     x0 = ap[k0];
        if (k0 + 1 < K) x1 = ap[k0 + 1];
    }
    uint32_t hw, lw;
    packpair(x0, x1, hw, lw);
    g_ah[t] = hw;
    g_al[t] = lw;
}

// Concat(B0[K,N0c], B1[K,N1c]) transposed -> g_bh/g_bl [n][stride] K-pair-major.
__global__ void cvt_wT_kernel(const float* __restrict__ B0, int N0c,
                              const float* __restrict__ B1, int N1c,
                              int K, int Np, int stride) {
    int t = blockIdx.x * blockDim.x + threadIdx.x;
    if (t >= Np * stride) return;
    int kp = t / Np, n = t - kp * Np;
    int k0 = kp * 2;
    float x0 = 0.f, x1 = 0.f;
    if (n < N0c) {
        if (k0 < K)     x0 = B0[(size_t)k0 * N0c + n];
        if (k0 + 1 < K) x1 = B0[(size_t)(k0 + 1) * N0c + n];
    } else if (B1 != nullptr && n - N0c < N1c) {
        int nn = n - N0c;
        if (k0 < K)     x0 = B1[(size_t)k0 * N1c + nn];
        if (k0 + 1 < K) x1 = B1[(size_t)(k0 + 1) * N1c + nn];
    }
    uint32_t hw, lw;
    packpair(x0, x1, hw, lw);
    size_t o = (size_t)n * stride + kp;
    g_bh[o] = hw;
    g_bl[o] = lw;
}

// ============================================================================
// bf16x3 tensor-core GEMM, ldmatrix fragments, cp.async pipeline.
// CTA tile 128x128, BK=32. 8 warps 2x4 -> warp tile 64x32 (4x4 m16n8k16 x3).
// smem: 4 planes (Ahi,Alo,Bhi,Blo), each 128 rows x (16 data + 4 pad) words.
// ============================================================================
#define PW 20                            // words per smem plane row
#define PLANE_W (128 * PW)               // 2560 words per plane
#define BUF_W (4 * PLANE_W)              // 10240 words per stage
#define GEMM_SMEM_BYTES (2 * BUF_W * 4)  // 81920 B

__device__ __forceinline__ void mma_bf16(float* c, const uint32_t* a,
                                         const uint32_t* b) {
    asm volatile(
        "mma.sync.aligned.m16n8k16.row.col.f32.bf16.bf16.f32 "
        "{%0,%1,%2,%3},{%4,%5,%6,%7},{%8,%9},{%0,%1,%2,%3};\n"
        : "+f"(c[0]), "+f"(c[1]), "+f"(c[2]), "+f"(c[3])
        : "r"(a[0]), "r"(a[1]), "r"(a[2]), "r"(a[3]), "r"(b[0]), "r"(b[1]));
}

__device__ __forceinline__ void ldsm4(uint32_t* r, uint32_t a) {
    asm volatile("ldmatrix.sync.aligned.m8n8.x4.shared.b16 {%0,%1,%2,%3}, [%4];"
                 : "=r"(r[0]), "=r"(r[1]), "=r"(r[2]), "=r"(r[3]) : "r"(a));
}
__device__ __forceinline__ void ldsm2(uint32_t* r, uint32_t a) {
    asm volatile("ldmatrix.sync.aligned.m8n8.x2.shared.b16 {%0,%1}, [%2];"
                 : "=r"(r[0]), "=r"(r[1]) : "r"(a));
}

__device__ __forceinline__ void cp16(uint32_t saddr, const void* g) {
    asm volatile("cp.async.cg.shared.global [%0], [%1], 16;\n"
                 :: "r"(saddr), "l"(g));
}

__global__ __launch_bounds__(256, 2) void mma_gemm_async(
    const uint32_t* __restrict__ Ah, const uint32_t* __restrict__ Al,
    const uint32_t* __restrict__ Bh, const uint32_t* __restrict__ Bl,
    float* __restrict__ C0, float* __restrict__ C1,
    int M, int aStride, int N0, int ld0, int N1, int ld1, int nkt) {
    extern __shared__ uint32_t sm[];
    const uint32_t smemBase = (uint32_t)__cvta_generic_to_shared(sm);
    const int tid  = threadIdx.x;
    const int warp = tid >> 5, lane = tid & 31;
    const int group = lane >> 2, tg = lane & 3;
    const int wM = (warp >> 2) * 64;
    const int wN = (warp & 3) * 32;
    const int tileM = blockIdx.y * 128;
    const int tileN = blockIdx.x * 128;

    // loader: thread covers plane row (tid>>1), 8-word half (tid&1)
    const int ldRow = tid >> 1, ldHalf = tid & 1;
    const size_t aGbase = (size_t)(tileM + ldRow) * aStride + ldHalf * 8;
    const size_t bGbase = (size_t)(tileN + ldRow) * aStride + ldHalf * 8;
    const uint32_t ldS = (ldRow * PW + ldHalf * 8) * 4;  // byte offset in plane

    // ldmatrix per-lane address pieces (word offsets within a plane)
    const uint32_t aOff = (wM + (lane & 15)) * PW + (lane >> 4) * 4;
    const uint32_t bOff = (wN + (lane & 7)) * PW + ((lane >> 3) & 1) * 4;

    auto issue = [&](int kt, int buf) {
        const uint32_t sb = smemBase + buf * (BUF_W * 4);
        const uint32_t* gs[4] = {Ah + aGbase, Al + aGbase, Bh + bGbase, Bl + bGbase};
#pragma unroll
        for (int p = 0; p < 4; p++) {
            const uint32_t* g = gs[p] + kt * 16;
            uint32_t d = sb + p * (PLANE_W * 4) + ldS;
            cp16(d, g);
            cp16(d + 16, g + 4);
        }
        asm volatile("cp.async.commit_group;\n");
    };

    float acc[4][4][4] = {};

    issue(0, 0);
    if (nkt > 1) issue(1, 1);

    for (int t = 0; t < nkt; t++) {
        const int cur = t & 1;
        if (t + 1 < nkt)
            asm volatile("cp.async.wait_group 1;\n");
        else
            asm volatile("cp.async.wait_group 0;\n");
        __syncthreads();

        const uint32_t sb = smemBase + cur * (BUF_W * 4);
#pragma unroll
        for (int ks = 0; ks < 2; ks++) {
            const uint32_t kb2 = ks * 8;
            uint32_t afr[4][2][4];
#pragma unroll
            for (int i = 0; i < 4; i++)
#pragma unroll
                for (int p = 0; p < 2; p++)
                    ldsm4(afr[i][p],
                          sb + p * (PLANE_W * 4) + (aOff + i * 16 * PW + kb2) * 4);
            uint32_t bfr[4][2][2];
#pragma unroll
            for (int j = 0; j < 4; j++)
#pragma unroll
                for (int p = 0; p < 2; p++)
                    ldsm2(bfr[j][p],
                          sb + (2 + p) * (PLANE_W * 4) + (bOff + j * 8 * PW + kb2) * 4);
            // three independent sweeps: consecutive MMAs hit different accs
#pragma unroll
            for (int i = 0; i < 4; i++)
#pragma unroll
                for (int j = 0; j < 4; j++)
                    mma_bf16(acc[i][j], afr[i][0], bfr[j][0]);  // hi*hi
#pragma unroll
            for (int i = 0; i < 4; i++)
#pragma unroll
                for (int j = 0; j < 4; j++)
                    mma_bf16(acc[i][j], afr[i][0], bfr[j][1]);  // hi*lo
#pragma unroll
            for (int i = 0; i < 4; i++)
#pragma unroll
                for (int j = 0; j < 4; j++)
                    mma_bf16(acc[i][j], afr[i][1], bfr[j][0]);  // lo*hi
        }
        __syncthreads();
        if (t + 2 < nkt) issue(t + 2, cur);
    }

    // ---------------- epilogue: split store into C0 / C1 ----------------
    auto store = [&](int gm, int gn, float v) {
        if (gm >= M) return;
        if (gn < N0) {
            C0[(size_t)gm * ld0 + gn] = v;
        } else {
            int n2 = gn - N0;
            if (n2 < N1) C1[(size_t)gm * ld1 + n2] = v;
        }
    };
#pragma unroll
    for (int i = 0; i < 4; i++) {
        int row0 = tileM + wM + i * 16 + group;
#pragma unroll
        for (int j = 0; j < 4; j++) {
            int col0 = tileN + wN + j * 8 + tg * 2;
            store(row0,     col0,     acc[i][j][0]);
            store(row0,     col0 + 1, acc[i][j][1]);
            store(row0 + 8, col0,     acc[i][j][2]);
            store(row0 + 8, col0 + 1, acc[i][j][3]);
        }
    }
}

// ---------------- per-node attention logits ---------------------------------
__global__ void compute_alpha_kernel(const float* __restrict__ xl,
                                     const float* __restrict__ a_src,
                                     const float* __restrict__ a_dst,
                                     int H, int C, int LD) {
    int n = blockIdx.x;
    int h = threadIdx.x >> 5;
    int lane = threadIdx.x & 31;
    const float* xr = xl + (size_t)n * LD + h * C;
    float ss = 0.f, sd = 0.f;
    for (int c = lane; c < C; c += 32) {
        float v = xr[c];
        ss += v * a_src[h * C + c];
        sd += v * a_dst[h * C + c];
    }
#pragma unroll
    for (int off = 16; off > 0; off >>= 1) {
        ss += __shfl_down_sync(0xffffffffu, ss, off);
        sd += __shfl_down_sync(0xffffffffu, sd, off);
    }
    if (lane == 0) {
        g_asrc[n * H + h] = ss;
        g_adst[n * H + h] = sd;
    }
}

// ---------------- edge softmax: weights + denominator (CSR order) ------------
__global__ void edge_softmax_kernel(int H) {
    int d = blockIdx.x;
    int h = threadIdx.x >> 5;
    int lane = threadIdx.x & 31;
    int r0 = g_row[d], r1 = g_row[d + 1];
    float adv = g_adst[d * H + h];

    float mx = -1e30f;
    for (int j = r0 + lane; j < r1; j += 32)
        mx = fmaxf(mx, g_asrc[g_csr_src[j] * H + h]);
#pragma unroll
    for (int off = 16; off > 0; off >>= 1)
        mx = fmaxf(mx, __shfl_xor_sync(0xffffffffu, mx, off));
    float m = mx + adv;
    m = (m > 0.f) ? m : 0.2f * m;  // leaky relu commutes with max (monotonic)

    float sum = 0.f;
    for (int j = r0 + lane; j < r1; j += 32) {
        float e = g_asrc[g_csr_src[j] * H + h] + adv;
        e = (e > 0.f) ? e : 0.2f * e;
        float w = __expf(e - m);
        g_walpha[(size_t)j * H + h] = w;
        sum += w;
    }
#pragma unroll
    for (int off = 16; off > 0; off >>= 1)
        sum += __shfl_xor_sync(0xffffffffu, sum, off);
    if (lane == 0) g_adenom[d * H + h] = sum;
}

// ---------------- gather: one block per dst, all heads, float4 ---------------
template <bool ALIGNED>
__global__ void gat_gather_kernel(const float* __restrict__ xl,
                                  float* __restrict__ out,
                                  int H, int C, int LD, int HC) {
    int d = blockIdx.x;
    int tid = threadIdx.x;
    int f = tid * 4;
    int r0 = g_row[d], r1 = g_row[d + 1];

    int h0, h1, h2, h3;
    bool active;
    if (ALIGNED) {
        h0 = h1 = h2 = h3 = f / C;
        active = true;
    } else {
        active = (f < HC);
        h0 = min(f / C, H - 1);
        h1 = min((f + 1) / C, H - 1);
        h2 = min((f + 2) / C, H - 1);
        h3 = min((f + 3) / C, H - 1);
    }

    float4 acc = make_float4(0.f, 0.f, 0.f, 0.f);
    int j = r0;
    if (active) {
        for (; j + 1 < r1; j += 2) {
            int s0 = g_csr_src[j], s1 = g_csr_src[j + 1];
            const float* wp0 = &g_walpha[(size_t)j * H];
            const float* wp1 = &g_walpha[(size_t)(j + 1) * H];
            float4 v0 = *(reinterpret_cast<const float4*>(xl + (size_t)s0 * LD) + tid);
            float4 v1 = *(reinterpret_cast<const float4*>(xl + (size_t)s1 * LD) + tid);
            if (ALIGNED) {
                float w0 = wp0[h0], w1 = wp1[h0];
                acc.x += w0 * v0.x + w1 * v1.x;
                acc.y += w0 * v0.y + w1 * v1.y;
                acc.z += w0 * v0.z + w1 * v1.z;
                acc.w += w0 * v0.w + w1 * v1.w;
            } else {
                acc.x += wp0[h0] * v0.x + wp1[h0] * v1.x;
                acc.y += wp0[h1] * v0.y + wp1[h1] * v1.y;
                acc.z += wp0[h2] * v0.z + wp1[h2] * v1.z;
                acc.w += wp0[h3] * v0.w + wp1[h3] * v1.w;
            }
        }
        if (j < r1) {
            int s0 = g_csr_src[j];
            const float* wp0 = &g_walpha[(size_t)j * H];
            float4 v0 = *(reinterpret_cast<const float4*>(xl + (size_t)s0 * LD) + tid);
            acc.x += wp0[h0] * v0.x;
            acc.y += wp0[h1] * v0.y;
            acc.z += wp0[h2] * v0.z;
            acc.w += wp0[h3] * v0.w;
        }
    }

    if (!active) return;
    const float* dn = &g_adenom[d * H];
    float* o = out + (size_t)d * LD;
    if (ALIGNED) {
        float inv = 1.f / (dn[h0] + 1e-16f);
        float4 r = make_float4(acc.x * inv, acc.y * inv, acc.z * inv, acc.w * inv);
        *(reinterpret_cast<float4*>(o + f)) = r;
    } else {
        if (f < HC)     o[f]     = acc.x / (dn[h0] + 1e-16f);
        if (f + 1 < HC) o[f + 1] = acc.y / (dn[h1] + 1e-16f);
        if (f + 2 < HC) o[f + 2] = acc.z / (dn[h2] + 1e-16f);
        if (f + 3 < HC) o[f + 3] = acc.w / (dn[h3] + 1e-16f);
    }
}

// ---------------- fused add-skip + layernorm + elu -> packed bf16 planes -----
__global__ __launch_bounds__(256) void ln_elu_pack_kernel(
    const float* __restrict__ agg, const float* __restrict__ b,
    const float* __restrict__ skip, const float* __restrict__ skipb,
    const float* __restrict__ g, const float* __restrict__ beta) {
    int row = blockIdx.x;
    int tid = threadIdx.x;
    const size_t base = (size_t)row * 1024;
    int f = tid * 4;
    float4 a4 = *(const float4*)(agg + base + f);
    float4 s4 = *(const float4*)(skip + base + f);
    float4 b4 = *(const float4*)(b + f);
    float4 sb4 = *(const float4*)(skipb + f);
    float pre[4] = {a4.x + s4.x + b4.x + sb4.x, a4.y + s4.y + b4.y + sb4.y,
                    a4.z + s4.z + b4.z + sb4.z, a4.w + s4.w + b4.w + sb4.w};
    float sum = pre[0] + pre[1] + pre[2] + pre[3];
    __shared__ float red[256];
    red[tid] = sum;
    __syncthreads();
    for (int s = 128; s > 0; s >>= 1) {
        if (tid < s) red[tid] += red[tid + s];
        __syncthreads();
    }
    float mu = red[0] * (1.f / 1024.f);
    __syncthreads();
    float sq = 0.f;
#pragma unroll
    for (int k = 0; k < 4; k++) {
        float dlt = pre[k] - mu;
        sq += dlt * dlt;
    }
    red[tid] = sq;
    __syncthreads();
    for (int s = 128; s > 0; s >>= 1) {
        if (tid < s) red[tid] += red[tid + s];
        __syncthreads();
    }
    float rstd = rsqrtf(red[0] * (1.f / 1024.f) + 1e-5f);
    float4 g4 = *(const float4*)(g + f);
    float4 be4 = *(const float4*)(beta + f);
    float y[4];
    y[0] = (pre[0] - mu) * rstd * g4.x + be4.x;
    y[1] = (pre[1] - mu) * rstd * g4.y + be4.y;
    y[2] = (pre[2] - mu) * rstd * g4.z + be4.z;
    y[3] = (pre[3] - mu) * rstd * g4.w + be4.w;
#pragma unroll
    for (int k = 0; k < 4; k++) y[k] = (y[k] > 0.f) ? y[k] : expm1f(y[k]);
    uint32_t hw0, lw0, hw1, lw1;
    packpair(y[0], y[1], hw0, lw0);
    packpair(y[2], y[3], hw1, lw1);
    size_t w = (size_t)row * 512 + 2 * tid;
    g_ah[w] = hw0; g_ah[w + 1] = hw1;
    g_al[w] = lw0; g_al[w + 1] = lw1;
}

// ---------------- final head-mean + bias -------------------------------------
__global__ void head_mean_kernel(const float* __restrict__ agg,
                                 const float* __restrict__ b3,
                                 float* __restrict__ out) {
    int idx = blockIdx.x * blockDim.x + threadIdx.x;
    if (idx >= NN * 121) return;
    int n = idx / 121, c = idx % 121;
    float s = 0.f;
#pragma unroll
    for (int h = 0; h < 6; h++) s += agg[(size_t)n * 728 + h * 121 + c];
    out[idx] = s * (1.f / 6.f) + b3[c];
}

// ---------------- host orchestration -----------------------------------------
extern "C" void kernel_launch(void* const* d_in, const int* in_sizes, int n_in,
                              void* d_out, int out_size) {
    const float* x      = (const float*)d_in[0];
    const void*  ei     = d_in[1];
    const float* W1     = (const float*)d_in[2];
    const float* a_src1 = (const float*)d_in[3];
    const float* a_dst1 = (const float*)d_in[4];
    const float* b1     = (const float*)d_in[5];
    const float* W2     = (const float*)d_in[6];
    const float* a_src2 = (const float*)d_in[7];
    const float* a_dst2 = (const float*)d_in[8];
    const float* b2     = (const float*)d_in[9];
    const float* W3     = (const float*)d_in[10];
    const float* a_src3 = (const float*)d_in[11];
    const float* a_dst3 = (const float*)d_in[12];
    const float* b3     = (const float*)d_in[13];
    const float* skipW1 = (const float*)d_in[14];
    const float* skipb1 = (const float*)d_in[15];
    const float* skipW2 = (const float*)d_in[16];
    const float* skipb2 = (const float*)d_in[17];
    const float* g1     = (const float*)d_in[18];
    const float* beta1  = (const float*)d_in[19];
    const float* g2     = (const float*)d_in[20];
    const float* beta2  = (const float*)d_in[21];
    float* out = (float*)d_out;

    float *p_xl, *p_skip, *p_agg;
    uint32_t *p_ah, *p_al, *p_bh, *p_bl;
    cudaGetSymbolAddress((void**)&p_xl, g_xl);
    cudaGetSymbolAddress((void**)&p_skip, g_skip);
    cudaGetSymbolAddress((void**)&p_agg, g_agg);
    cudaGetSymbolAddress((void**)&p_ah, g_ah);
    cudaGetSymbolAddress((void**)&p_al, g_al);
    cudaGetSymbolAddress((void**)&p_bh, g_bh);
    cudaGetSymbolAddress((void**)&p_bl, g_bl);

    cudaFuncSetAttribute(mma_gemm_async,
                         cudaFuncAttributeMaxDynamicSharedMemorySize,
                         GEMM_SMEM_BYTES);

    // ---- CSR build (edges shared by all 3 layers) ----
    detect_dtype_kernel<<<1, 32>>>((const int*)ei);
    zero_deg_kernel<<<(NN + 255) / 256, 256>>>();
    build_edges_kernel<<<(NT + 255) / 256, 256>>>(ei);
    scan_kernel<<<1, 1024>>>();
    scatter_kernel<<<(NT + 255) / 256, 256>>>();

    const int gridM = MPAD / 128;   // 157

    // ---- Layer 1: GATConv(50 -> 256, H=4, concat) + skip; K=50 Kpad=64 ----
    {
        const int K = 50, aStride = 32, nkt = 2, Np = 2048;
        cvt_wT_kernel<<<((Np * aStride) + 255) / 256, 256>>>(
            W1, 1024, skipW1, 1024, K, Np, aStride);
        cvt_a_kernel<<<((MPAD * aStride) + 255) / 256, 256>>>(x, NN, K, aStride);
        mma_gemm_async<<<dim3(16, gridM), 256, GEMM_SMEM_BYTES>>>(
            p_ah, p_al, p_bh, p_bl, p_xl, p_skip, NN, aStride,
            1024, 1024, 1024, 1024, nkt);
    }
    compute_alpha_kernel<<<NN, 4 * 32>>>(p_xl, a_src1, a_dst1, 4, 256, 1024);
    edge_softmax_kernel<<<NN, 4 * 32>>>(4);
    gat_gather_kernel<true><<<NN, 256>>>(p_xl, p_agg, 4, 256, 1024, 1024);
    ln_elu_pack_kernel<<<NN, 256>>>(p_agg, b1, p_skip, skipb1, g1, beta1);

    // ---- Layer 2: GATConv(1024 -> 256, H=4, concat) + skip ----
    {
        const int aStride = 512, nkt = 32, Np = 2048;
        cvt_wT_kernel<<<((Np * aStride) + 255) / 256, 256>>>(
            W2, 1024, skipW2, 1024, 1024, Np, aStride);
        mma_gemm_async<<<dim3(16, gridM), 256, GEMM_SMEM_BYTES>>>(
            p_ah, p_al, p_bh, p_bl, p_xl, p_skip, NN, aStride,
            1024, 1024, 1024, 1024, nkt);
    }
    compute_alpha_kernel<<<NN, 4 * 32>>>(p_xl, a_src2, a_dst2, 4, 256, 1024);
    edge_softmax_kernel<<<NN, 4 * 32>>>(4);
    gat_gather_kernel<true><<<NN, 256>>>(p_xl, p_agg, 4, 256, 1024, 1024);
    ln_elu_pack_kernel<<<NN, 256>>>(p_agg, b2, p_skip, skipb2, g2, beta2);

    // ---- Layer 3: GATConv(1024 -> 121, H=6, mean); N=726, row stride 728 ----
    {
        const int aStride = 512, nkt = 32, Np = 768;
        cvt_wT_kernel<<<((Np * aStride) + 255) / 256, 256>>>(
            W3, 726, (const float*)nullptr, 0, 1024, Np, aStride);
        mma_gemm_async<<<dim3(6, gridM), 256, GEMM_SMEM_BYTES>>>(
            p_ah, p_al, p_bh, p_bl, p_xl, p_xl, NN, aStride,
            726, 728, 0, 728, nkt);
    }
    compute_alpha_kernel<<<NN, 6 * 32>>>(p_xl, a_src3, a_dst3, 6, 121, 728);
    edge_softmax_kernel<<<NN, 6 * 32>>>(6);
    gat_gather_kernel<false><<<NN, 192>>>(p_xl, p_agg, 6, 121, 728, 726);
    head_mean_kernel<<<(NN * 121 + 255) / 256, 256>>>(p_agg, b3, out);
}

// round 13
// speedup vs baseline: 1.0392x; 1.0392x over previous
#include <cuda_runtime.h>
#include <cuda_bf16.h>
#include <cstdint>

#define NN 20000
#define MPAD 20096              // NN rounded up to 128
#define NE 320000
#define NT (NE + NN)

// ---------------- scratch (device globals; no allocations allowed) ----------
__device__ float g_xl[(size_t)NN * 1024];
__device__ float g_skip[(size_t)NN * 1024];
__device__ float g_agg[(size_t)NN * 1024];
__device__ uint32_t g_ah[(size_t)MPAD * 512];   // packed bf16-hi A plane
__device__ uint32_t g_al[(size_t)MPAD * 512];   // packed bf16-lo A plane
__device__ uint32_t g_bh[(size_t)512 * 2048];   // packed bf16-hi B plane [kp][n]
__device__ uint32_t g_bl[(size_t)512 * 2048];   // packed bf16-lo B plane
__device__ float g_asrc[NN * 6];
__device__ float g_adst[NN * 6];
__device__ float g_walpha[(size_t)NT * 6];      // unnormalized softmax weights (CSR order)
__device__ float g_adenom[NN * 6];
__device__ int   g_deg[NN];
__device__ int   g_row[NN + 1];
__device__ int   g_cursor[NN];
__device__ int   g_esrc[NT];
__device__ int   g_edst[NT];
__device__ int   g_csr_src[NT];
__device__ int   g_is64;

// ---------------- edge dtype detection --------------------------------------
__global__ void detect_dtype_kernel(const int* __restrict__ w) {
    if (threadIdx.x == 0) {
        int nz = 0;
        for (int i = 1; i < 2048; i += 2) nz += (w[i] != 0);
        g_is64 = (nz == 0) ? 1 : 0;
    }
}

// ---------------- graph construction ----------------------------------------
__global__ void zero_deg_kernel() {
    int i = blockIdx.x * blockDim.x + threadIdx.x;
    if (i < NN) g_deg[i] = 0;
}

__global__ void build_edges_kernel(const void* __restrict__ ei) {
    int t = blockIdx.x * blockDim.x + threadIdx.x;
    if (t >= NT) return;
    int s, d;
    if (t < NE) {
        if (g_is64) {
            const long long* p = (const long long*)ei;
            s = (int)p[t];
            d = (int)p[NE + t];
        } else {
            const int* p = (const int*)ei;
            s = p[t];
            d = p[NE + t];
        }
        s = min(max(s, 0), NN - 1);
        d = min(max(d, 0), NN - 1);
    } else {
        s = d = t - NE;  // self loop
    }
    g_esrc[t] = s;
    g_edst[t] = d;
    atomicAdd(&g_deg[d], 1);
}

// warp-shuffle hierarchical scan (3 syncs per 1024-chunk)
__global__ void scan_kernel() {
    __shared__ int wsum[32];
    __shared__ int carry;
    int tid = threadIdx.x, lane = tid & 31, wid = tid >> 5;
    if (tid == 0) { carry = 0; g_row[0] = 0; }
    __syncthreads();
    for (int base = 0; base < NN; base += 1024) {
        int i = base + tid;
        int v = (i < NN) ? g_deg[i] : 0;
        int val = v;
#pragma unroll
        for (int off = 1; off < 32; off <<= 1) {
            int t = __shfl_up_sync(0xffffffffu, val, off);
            if (lane >= off) val += t;
        }
        if (lane == 31) wsum[wid] = val;
        __syncthreads();
        if (wid == 0) {
            int s = wsum[lane];
#pragma unroll
            for (int off = 1; off < 32; off <<= 1) {
                int t = __shfl_up_sync(0xffffffffu, s, off);
                if (lane >= off) s += t;
            }
            wsum[lane] = s;
        }
        __syncthreads();
        int prefix = carry + (wid > 0 ? wsum[wid - 1] : 0);
        int incl = prefix + val;
        if (i < NN) {
            g_row[i + 1] = incl;
            g_cursor[i]  = incl - v;
        }
        __syncthreads();
        if (tid == 0) carry += wsum[31];
        __syncthreads();
    }
}

__global__ void scatter_kernel() {
    int t = blockIdx.x * blockDim.x + threadIdx.x;
    if (t >= NT) return;
    int d = g_edst[t];
    int pos = atomicAdd(&g_cursor[d], 1);
    g_csr_src[pos] = g_esrc[t];
}

// ============================================================================
// hi/lo bf16 pre-conversion
// ============================================================================
__device__ __forceinline__ void packpair(float x0, float x1,
                                         uint32_t& hw, uint32_t& lw) {
    uint32_t b0 = __float_as_uint(x0), b1 = __float_as_uint(x1);
    uint32_t h0 = b0 & 0xFFFF0000u, h1 = b1 & 0xFFFF0000u;
    float l0 = x0 - __uint_as_float(h0);
    float l1 = x1 - __uint_as_float(h1);
    __nv_bfloat16 lb0 = __float2bfloat16(l0);
    __nv_bfloat16 lb1 = __float2bfloat16(l1);
    uint16_t u0 = *reinterpret_cast<uint16_t*>(&lb0);
    uint16_t u1 = *reinterpret_cast<uint16_t*>(&lb1);
    hw = (h0 >> 16) | h1;
    lw = (uint32_t)u0 | ((uint32_t)u1 << 16);
}

// A[M,K] fp32 -> packed word planes g_ah/g_al [MPAD][aStride]; zero pad.
__global__ void cvt_a_kernel(const float* __restrict__ A, int M, int K,
                             int aStride) {
    int t = blockIdx.x * blockDim.x + threadIdx.x;
    if (t >= MPAD * aStride) return;
    int row = t / aStride, kp = t - row * aStride;
    float x0 = 0.f, x1 = 0.f;
    if (row < M) {
        int k0 = kp * 2;
        const float* ap = &A[(size_t)row * K];
        if (k0 < K)     x0 = ap[k0];
        if (k0 + 1 < K) x1 = ap[k0 + 1];
    }
    uint32_t hw, lw;
    packpair(x0, x1, hw, lw);
    g_ah[t] = hw;
    g_al[t] = lw;
}

// Concat(B0[K,N0c], B1[K,N1c]) -> packed k-pair planes g_bh/g_bl [kpHalf][Np].
__global__ void cvt_w_kernel(const float* __restrict__ B0, int N0c,
                             const float* __restrict__ B1, int N1c,
                             int K, int Np, int kpHalf) {
    int t = blockIdx.x * blockDim.x + threadIdx.x;
    if (t >= kpHalf * Np) return;
    int kp = t / Np, n = t - kp * Np;
    int k0 = kp * 2;
    float x0 = 0.f, x1 = 0.f;
    if (n < N0c) {
        if (k0 < K)     x0 = B0[(size_t)k0 * N0c + n];
        if (k0 + 1 < K) x1 = B0[(size_t)(k0 + 1) * N0c + n];
    } else if (B1 != nullptr && n - N0c < N1c) {
        int nn = n - N0c;
        if (k0 < K)     x0 = B1[(size_t)k0 * N1c + nn];
        if (k0 + 1 < K) x1 = B1[(size_t)(k0 + 1) * N1c + nn];
    }
    uint32_t hw, lw;
    packpair(x0, x1, hw, lw);
    g_bh[t] = hw;
    g_bl[t] = lw;
}

// ============================================================================
// bf16x3 tensor-core GEMM, pre-converted operands, cp.async pipeline.
// CTA tile 128x128, BK=32. 8 warps 2x4 -> warp tile 64x32 (4x4 m16n8k16 x3).
// (R11-proven configuration)
// ============================================================================
#define AW  20
#define BW  136
#define A_P_STRIDE (128 * AW)
#define B_P_STRIDE (16 * BW)
#define BUF_WORDS  (2 * A_P_STRIDE + 2 * B_P_STRIDE)
#define GEMM_SMEM_BYTES (2 * BUF_WORDS * 4)

__device__ __forceinline__ void mma_bf16(float* c, const uint32_t* a,
                                         const uint32_t* b) {
    asm volatile(
        "mma.sync.aligned.m16n8k16.row.col.f32.bf16.bf16.f32 "
        "{%0,%1,%2,%3},{%4,%5,%6,%7},{%8,%9},{%0,%1,%2,%3};\n"
        : "+f"(c[0]), "+f"(c[1]), "+f"(c[2]), "+f"(c[3])
        : "r"(a[0]), "r"(a[1]), "r"(a[2]), "r"(a[3]), "r"(b[0]), "r"(b[1]));
}

__device__ __forceinline__ void cp16(uint32_t saddr, const void* g) {
    asm volatile("cp.async.cg.shared.global [%0], [%1], 16;\n"
                 :: "r"(saddr), "l"(g));
}

__global__ __launch_bounds__(256, 2) void mma_gemm_async(
    const uint32_t* __restrict__ Ah, const uint32_t* __restrict__ Al,
    const uint32_t* __restrict__ Bh, const uint32_t* __restrict__ Bl,
    float* __restrict__ C0, float* __restrict__ C1,
    int M, int aStride, int Np, int N0, int ld0, int N1, int ld1, int nkt) {
    extern __shared__ uint32_t sm[];
    const int tid  = threadIdx.x;
    const int warp = tid >> 5, lane = tid & 31;
    const int group = lane >> 2, tg = lane & 3;
    const int wM = (warp >> 2) * 64;
    const int wN = (warp & 3) * 32;
    const int tileM = blockIdx.y * 128;
    const int tileN = blockIdx.x * 128;

    const int aRow = tid >> 1, aHalf = tid & 1;
    const size_t aGbase = (size_t)(tileM + aRow) * aStride + aHalf * 8;
    const uint32_t aSbase = aRow * AW + aHalf * 8;
    const int bKp = tid >> 4, bN0 = (tid & 15) * 8;
    const uint32_t bSbase = bKp * BW + bN0;

    auto issue = [&](int kt, int buf) {
        uint32_t* s = sm + buf * BUF_WORDS;
        {
            const uint32_t* gh = Ah + aGbase + kt * 16;
            const uint32_t* gl = Al + aGbase + kt * 16;
            uint32_t sh_ = (uint32_t)__cvta_generic_to_shared(s + aSbase);
            uint32_t sl_ = (uint32_t)__cvta_generic_to_shared(s + A_P_STRIDE + aSbase);
            cp16(sh_, gh); cp16(sh_ + 16, gh + 4);
            cp16(sl_, gl); cp16(sl_ + 16, gl + 4);
        }
        {
            const size_t go = (size_t)(kt * 16 + bKp) * Np + tileN + bN0;
            const uint32_t* gh = Bh + go;
            const uint32_t* gl = Bl + go;
            uint32_t* bs = s + 2 * A_P_STRIDE;
            uint32_t sh_ = (uint32_t)__cvta_generic_to_shared(bs + bSbase);
            uint32_t sl_ = (uint32_t)__cvta_generic_to_shared(bs + B_P_STRIDE + bSbase);
            cp16(sh_, gh); cp16(sh_ + 16, gh + 4);
            cp16(sl_, gl); cp16(sl_ + 16, gl + 4);
        }
    };

    float acc[4][4][4] = {};

    issue(0, 0);
    asm volatile("cp.async.commit_group;\n");

    for (int t = 0; t < nkt; t++) {
        const int cur = t & 1;
        const bool more = (t + 1 < nkt);
        if (more) {
            issue(t + 1, cur ^ 1);
            asm volatile("cp.async.commit_group;\n");
            asm volatile("cp.async.wait_group 1;\n");
        } else {
            asm volatile("cp.async.wait_group 0;\n");
        }
        __syncthreads();

        const uint32_t* As_ = sm + cur * BUF_WORDS;
        const uint32_t* Bs_ = sm + cur * BUF_WORDS + 2 * A_P_STRIDE;
#pragma unroll
        for (int ks = 0; ks < 2; ks++) {
            const int kb2 = ks * 8;
            uint32_t afr[4][2][4];
#pragma unroll
            for (int i = 0; i < 4; i++) {
                int row = wM + i * 16 + group;
#pragma unroll
                for (int p = 0; p < 2; p++) {
                    const uint32_t* Ap = As_ + p * A_P_STRIDE;
                    afr[i][p][0] = Ap[row * AW + kb2 + tg];
                    afr[i][p][1] = Ap[(row + 8) * AW + kb2 + tg];
                    afr[i][p][2] = Ap[row * AW + kb2 + 4 + tg];
                    afr[i][p][3] = Ap[(row + 8) * AW + kb2 + 4 + tg];
                }
            }
            uint32_t bfr[4][2][2];
#pragma unroll
            for (int j = 0; j < 4; j++) {
                int n = wN + j * 8 + group;
#pragma unroll
                for (int p = 0; p < 2; p++) {
                    const uint32_t* Bp = Bs_ + p * B_P_STRIDE;
                    bfr[j][p][0] = Bp[(kb2 + tg) * BW + n];
                    bfr[j][p][1] = Bp[(kb2 + 4 + tg) * BW + n];
                }
            }
            // three independent sweeps: consecutive MMAs hit different accs
#pragma unroll
            for (int i = 0; i < 4; i++)
#pragma unroll
                for (int j = 0; j < 4; j++)
                    mma_bf16(acc[i][j], afr[i][0], bfr[j][0]);  // hi*hi
#pragma unroll
            for (int i = 0; i < 4; i++)
#pragma unroll
                for (int j = 0; j < 4; j++)
                    mma_bf16(acc[i][j], afr[i][0], bfr[j][1]);  // hi*lo
#pragma unroll
            for (int i = 0; i < 4; i++)
#pragma unroll
                for (int j = 0; j < 4; j++)
                    mma_bf16(acc[i][j], afr[i][1], bfr[j][0]);  // lo*hi
        }
        __syncthreads();
    }

    // ---------------- epilogue: split store into C0 / C1 ----------------
    auto store = [&](int gm, int gn, float v) {
        if (gm >= M) return;
        if (gn < N0) {
            C0[(size_t)gm * ld0 + gn] = v;
        } else {
            int n2 = gn - N0;
            if (n2 < N1) C1[(size_t)gm * ld1 + n2] = v;
        }
    };
#pragma unroll
    for (int i = 0; i < 4; i++) {
        int row0 = tileM + wM + i * 16 + group;
#pragma unroll
        for (int j = 0; j < 4; j++) {
            int col0 = tileN + wN + j * 8 + tg * 2;
            store(row0,     col0,     acc[i][j][0]);
            store(row0,     col0 + 1, acc[i][j][1]);
            store(row0 + 8, col0,     acc[i][j][2]);
            store(row0 + 8, col0 + 1, acc[i][j][3]);
        }
    }
}

// ---------------- per-node attention logits ---------------------------------
__global__ void compute_alpha_kernel(const float* __restrict__ xl,
                                     const float* __restrict__ a_src,
                                     const float* __restrict__ a_dst,
                                     int H, int C, int LD) {
    int n = blockIdx.x;
    int h = threadIdx.x >> 5;
    int lane = threadIdx.x & 31;
    const float* xr = xl + (size_t)n * LD + h * C;
    float ss = 0.f, sd = 0.f;
    for (int c = lane; c < C; c += 32) {
        float v = xr[c];
        ss += v * a_src[h * C + c];
        sd += v * a_dst[h * C + c];
    }
#pragma unroll
    for (int off = 16; off > 0; off >>= 1) {
        ss += __shfl_down_sync(0xffffffffu, ss, off);
        sd += __shfl_down_sync(0xffffffffu, sd, off);
    }
    if (lane == 0) {
        g_asrc[n * H + h] = ss;
        g_adst[n * H + h] = sd;
    }
}

// ---------------- edge softmax: weights + denominator (CSR order) ------------
__global__ void edge_softmax_kernel(int H) {
    int d = blockIdx.x;
    int h = threadIdx.x >> 5;
    int lane = threadIdx.x & 31;
    int r0 = g_row[d], r1 = g_row[d + 1];
    float adv = g_adst[d * H + h];

    float mx = -1e30f;
    for (int j = r0 + lane; j < r1; j += 32)
        mx = fmaxf(mx, g_asrc[g_csr_src[j] * H + h]);
#pragma unroll
    for (int off = 16; off > 0; off >>= 1)
        mx = fmaxf(mx, __shfl_xor_sync(0xffffffffu, mx, off));
    float m = mx + adv;
    m = (m > 0.f) ? m : 0.2f * m;  // leaky relu commutes with max (monotonic)

    float sum = 0.f;
    for (int j = r0 + lane; j < r1; j += 32) {
        float e = g_asrc[g_csr_src[j] * H + h] + adv;
        e = (e > 0.f) ? e : 0.2f * e;
        float w = __expf(e - m);
        g_walpha[(size_t)j * H + h] = w;
        sum += w;
    }
#pragma unroll
    for (int off = 16; off > 0; off >>= 1)
        sum += __shfl_xor_sync(0xffffffffu, sum, off);
    if (lane == 0) g_adenom[d * H + h] = sum;
}

// ---------------- gather: one block per dst, all heads, float4, MLP=4 --------
template <bool ALIGNED>
__global__ void gat_gather_kernel(const float* __restrict__ xl,
                                  float* __restrict__ out,
                                  int H, int C, int LD, int HC) {
    int d = blockIdx.x;
    int tid = threadIdx.x;
    int f = tid * 4;
    int r0 = g_row[d], r1 = g_row[d + 1];

    int h0, h1, h2, h3;
    bool active;
    if (ALIGNED) {
        h0 = h1 = h2 = h3 = f / C;
        active = true;
    } else {
        active = (f < HC);
        h0 = min(f / C, H - 1);
        h1 = min((f + 1) / C, H - 1);
        h2 = min((f + 2) / C, H - 1);
        h3 = min((f + 3) / C, H - 1);
    }

    float4 acc = make_float4(0.f, 0.f, 0.f, 0.f);
    int j = r0;
    if (active) {
        for (; j + 3 < r1; j += 4) {
            int s0 = g_csr_src[j],     s1 = g_csr_src[j + 1];
            int s2 = g_csr_src[j + 2], s3 = g_csr_src[j + 3];
            const float* wp0 = &g_walpha[(size_t)j * H];
            const float* wp1 = &g_walpha[(size_t)(j + 1) * H];
            const float* wp2 = &g_walpha[(size_t)(j + 2) * H];
            const float* wp3 = &g_walpha[(size_t)(j + 3) * H];
            float4 v0 = *(reinterpret_cast<const float4*>(xl + (size_t)s0 * LD) + tid);
            float4 v1 = *(reinterpret_cast<const float4*>(xl + (size_t)s1 * LD) + tid);
            float4 v2 = *(reinterpret_cast<const float4*>(xl + (size_t)s2 * LD) + tid);
            float4 v3 = *(reinterpret_cast<const float4*>(xl + (size_t)s3 * LD) + tid);
            if (ALIGNED) {
                float w0 = wp0[h0], w1 = wp1[h0], w2 = wp2[h0], w3 = wp3[h0];
                acc.x += w0 * v0.x + w1 * v1.x + w2 * v2.x + w3 * v3.x;
                acc.y += w0 * v0.y + w1 * v1.y + w2 * v2.y + w3 * v3.y;
                acc.z += w0 * v0.z + w1 * v1.z + w2 * v2.z + w3 * v3.z;
                acc.w += w0 * v0.w + w1 * v1.w + w2 * v2.w + w3 * v3.w;
            } else {
                acc.x += wp0[h0] * v0.x + wp1[h0] * v1.x + wp2[h0] * v2.x + wp3[h0] * v3.x;
                acc.y += wp0[h1] * v0.y + wp1[h1] * v1.y + wp2[h1] * v2.y + wp3[h1] * v3.y;
                acc.z += wp0[h2] * v0.z + wp1[h2] * v1.z + wp2[h2] * v2.z + wp3[h2] * v3.z;
                acc.w += wp0[h3] * v0.w + wp1[h3] * v1.w + wp2[h3] * v2.w + wp3[h3] * v3.w;
            }
        }
        for (; j < r1; j++) {
            int s0 = g_csr_src[j];
            const float* wp0 = &g_walpha[(size_t)j * H];
            float4 v0 = *(reinterpret_cast<const float4*>(xl + (size_t)s0 * LD) + tid);
            acc.x += wp0[h0] * v0.x;
            acc.y += wp0[h1] * v0.y;
            acc.z += wp0[h2] * v0.z;
            acc.w += wp0[h3] * v0.w;
        }
    }

    if (!active) return;
    const float* dn = &g_adenom[d * H];
    float* o = out + (size_t)d * LD;
    if (ALIGNED) {
        float inv = 1.f / (dn[h0] + 1e-16f);
        float4 r = make_float4(acc.x * inv, acc.y * inv, acc.z * inv, acc.w * inv);
        *(reinterpret_cast<float4*>(o + f)) = r;
    } else {
        if (f < HC)     o[f]     = acc.x / (dn[h0] + 1e-16f);
        if (f + 1 < HC) o[f + 1] = acc.y / (dn[h1] + 1e-16f);
        if (f + 2 < HC) o[f + 2] = acc.z / (dn[h2] + 1e-16f);
        if (f + 3 < HC) o[f + 3] = acc.w / (dn[h3] + 1e-16f);
    }
}

// ---------------- fused add-skip + layernorm + elu -> packed bf16 planes -----
__global__ __launch_bounds__(256) void ln_elu_pack_kernel(
    const float* __restrict__ agg, const float* __restrict__ b,
    const float* __restrict__ skip, const float* __restrict__ skipb,
    const float* __restrict__ g, const float* __restrict__ beta) {
    int row = blockIdx.x;
    int tid = threadIdx.x;
    const size_t base = (size_t)row * 1024;
    int f = tid * 4;
    float4 a4 = *(const float4*)(agg + base + f);
    float4 s4 = *(const float4*)(skip + base + f);
    float4 b4 = *(const float4*)(b + f);
    float4 sb4 = *(const float4*)(skipb + f);
    float pre[4] = {a4.x + s4.x + b4.x + sb4.x, a4.y + s4.y + b4.y + sb4.y,
                    a4.z + s4.z + b4.z + sb4.z, a4.w + s4.w + b4.w + sb4.w};
    float sum = pre[0] + pre[1] + pre[2] + pre[3];
    __shared__ float red[256];
    red[tid] = sum;
    __syncthreads();
    for (int s = 128; s > 0; s >>= 1) {
        if (tid < s) red[tid] += red[tid + s];
        __syncthreads();
    }
    float mu = red[0] * (1.f / 1024.f);
    __syncthreads();
    float sq = 0.f;
#pragma unroll
    for (int k = 0; k < 4; k++) {
        float dlt = pre[k] - mu;
        sq += dlt * dlt;
    }
    red[tid] = sq;
    __syncthreads();
    for (int s = 128; s > 0; s >>= 1) {
        if (tid < s) red[tid] += red[tid + s];
        __syncthreads();
    }
    float rstd = rsqrtf(red[0] * (1.f / 1024.f) + 1e-5f);
    float4 g4 = *(const float4*)(g + f);
    float4 be4 = *(const float4*)(beta + f);
    float y[4];
    y[0] = (pre[0] - mu) * rstd * g4.x + be4.x;
    y[1] = (pre[1] - mu) * rstd * g4.y + be4.y;
    y[2] = (pre[2] - mu) * rstd * g4.z + be4.z;
    y[3] = (pre[3] - mu) * rstd * g4.w + be4.w;
#pragma unroll
    for (int k = 0; k < 4; k++) y[k] = (y[k] > 0.f) ? y[k] : expm1f(y[k]);
    uint32_t hw0, lw0, hw1, lw1;
    packpair(y[0], y[1], hw0, lw0);
    packpair(y[2], y[3], hw1, lw1);
    size_t w = (size_t)row * 512 + 2 * tid;
    g_ah[w] = hw0; g_ah[w + 1] = hw1;
    g_al[w] = lw0; g_al[w + 1] = lw1;
}

// ---------------- final head-mean + bias -------------------------------------
__global__ void head_mean_kernel(const float* __restrict__ agg,
                                 const float* __restrict__ b3,
                                 float* __restrict__ out) {
    int idx = blockIdx.x * blockDim.x + threadIdx.x;
    if (idx >= NN * 121) return;
    int n = idx / 121, c = idx % 121;
    float s = 0.f;
#pragma unroll
    for (int h = 0; h < 6; h++) s += agg[(size_t)n * 728 + h * 121 + c];
    out[idx] = s * (1.f / 6.f) + b3[c];
}

// ---------------- host orchestration -----------------------------------------
extern "C" void kernel_launch(void* const* d_in, const int* in_sizes, int n_in,
                              void* d_out, int out_size) {
    const float* x      = (const float*)d_in[0];
    const void*  ei     = d_in[1];
    const float* W1     = (const float*)d_in[2];
    const float* a_src1 = (const float*)d_in[3];
    const float* a_dst1 = (const float*)d_in[4];
    const float* b1     = (const float*)d_in[5];
    const float* W2     = (const float*)d_in[6];
    const float* a_src2 = (const float*)d_in[7];
    const float* a_dst2 = (const float*)d_in[8];
    const float* b2     = (const float*)d_in[9];
    const float* W3     = (const float*)d_in[10];
    const float* a_src3 = (const float*)d_in[11];
    const float* a_dst3 = (const float*)d_in[12];
    const float* b3     = (const float*)d_in[13];
    const float* skipW1 = (const float*)d_in[14];
    const float* skipb1 = (const float*)d_in[15];
    const float* skipW2 = (const float*)d_in[16];
    const float* skipb2 = (const float*)d_in[17];
    const float* g1     = (const float*)d_in[18];
    const float* beta1  = (const float*)d_in[19];
    const float* g2     = (const float*)d_in[20];
    const float* beta2  = (const float*)d_in[21];
    float* out = (float*)d_out;

    float *p_xl, *p_skip, *p_agg;
    uint32_t *p_ah, *p_al, *p_bh, *p_bl;
    cudaGetSymbolAddress((void**)&p_xl, g_xl);
    cudaGetSymbolAddress((void**)&p_skip, g_skip);
    cudaGetSymbolAddress((void**)&p_agg, g_agg);
    cudaGetSymbolAddress((void**)&p_ah, g_ah);
    cudaGetSymbolAddress((void**)&p_al, g_al);
    cudaGetSymbolAddress((void**)&p_bh, g_bh);
    cudaGetSymbolAddress((void**)&p_bl, g_bl);

    cudaFuncSetAttribute(mma_gemm_async,
                         cudaFuncAttributeMaxDynamicSharedMemorySize,
                         GEMM_SMEM_BYTES);

    // ---- CSR build (edges shared by all 3 layers) ----
    detect_dtype_kernel<<<1, 32>>>((const int*)ei);
    zero_deg_kernel<<<(NN + 255) / 256, 256>>>();
    build_edges_kernel<<<(NT + 255) / 256, 256>>>(ei);
    scan_kernel<<<1, 1024>>>();
    scatter_kernel<<<(NT + 255) / 256, 256>>>();

    const int gridM = MPAD / 128;   // 157

    // ---- Layer 1: GATConv(50 -> 256, H=4, concat) + skip; K=50 Kpad=64 ----
    {
        const int K = 50, aStride = 32, nkt = 2, Np = 2048;
        cvt_w_kernel<<<((Np * aStride) + 255) / 256, 256>>>(
            W1, 1024, skipW1, 1024, K, Np, aStride);
        cvt_a_kernel<<<((MPAD * aStride) + 255) / 256, 256>>>(x, NN, K, aStride);
        mma_gemm_async<<<dim3(16, gridM), 256, GEMM_SMEM_BYTES>>>(
            p_ah, p_al, p_bh, p_bl, p_xl, p_skip, NN, aStride, Np,
            1024, 1024, 1024, 1024, nkt);
    }
    compute_alpha_kernel<<<NN, 4 * 32>>>(p_xl, a_src1, a_dst1, 4, 256, 1024);
    edge_softmax_kernel<<<NN, 4 * 32>>>(4);
    gat_gather_kernel<true><<<NN, 256>>>(p_xl, p_agg, 4, 256, 1024, 1024);
    ln_elu_pack_kernel<<<NN, 256>>>(p_agg, b1, p_skip, skipb1, g1, beta1);

    // ---- Layer 2: GATConv(1024 -> 256, H=4, concat) + skip ----
    {
        const int aStride = 512, nkt = 32, Np = 2048;
        cvt_w_kernel<<<((Np * aStride) + 255) / 256, 256>>>(
            W2, 1024, skipW2, 1024, 1024, Np, aStride);
        mma_gemm_async<<<dim3(16, gridM), 256, GEMM_SMEM_BYTES>>>(
            p_ah, p_al, p_bh, p_bl, p_xl, p_skip, NN, aStride, Np,
            1024, 1024, 1024, 1024, nkt);
    }
    compute_alpha_kernel<<<NN, 4 * 32>>>(p_xl, a_src2, a_dst2, 4, 256, 1024);
    edge_softmax_kernel<<<NN, 4 * 32>>>(4);
    gat_gather_kernel<true><<<NN, 256>>>(p_xl, p_agg, 4, 256, 1024, 1024);
    ln_elu_pack_kernel<<<NN, 256>>>(p_agg, b2, p_skip, skipb2, g2, beta2);

    // ---- Layer 3: GATConv(1024 -> 121, H=6, mean); N=726, row stride 728 ----
    {
        const int aStride = 512, nkt = 32, Np = 768;
        cvt_w_kernel<<<((Np * aStride) + 255) / 256, 256>>>(
            W3, 726, (const float*)nullptr, 0, 1024, Np, aStride);
        mma_gemm_async<<<dim3(6, gridM), 256, GEMM_SMEM_BYTES>>>(
            p_ah, p_al, p_bh, p_bl, p_xl, p_xl, NN, aStride, Np,
            726, 728, 0, 728, nkt);
    }
    compute_alpha_kernel<<<NN, 6 * 32>>>(p_xl, a_src3, a_dst3, 6, 121, 728);
    edge_softmax_kernel<<<NN, 6 * 32>>>(6);
    gat_gather_kernel<false><<<NN, 192>>>(p_xl, p_agg, 6, 121, 728, 726);
    head_mean_kernel<<<(NN * 121 + 255) / 256, 256>>>(p_agg, b3, out);
}

// round 14
// speedup vs baseline: 1.0397x; 1.0005x over previous
#include <cuda_runtime.h>
#include <cuda_bf16.h>
#include <cstdint>

#define NN 20000
#define MPAD 20096              // NN rounded up to 128
#define NE 320000
#define NT (NE + NN)

// ---------------- scratch (device globals; no allocations allowed) ----------
__device__ float g_xl[(size_t)NN * 1024];
__device__ float g_skip[(size_t)NN * 1024];
__device__ float g_agg[(size_t)NN * 1024];
__device__ uint32_t g_ah[(size_t)MPAD * 512];   // packed bf16-hi A plane
__device__ uint32_t g_al[(size_t)MPAD * 512];   // packed bf16-lo A plane
__device__ uint32_t g_bh[(size_t)512 * 2048];   // packed bf16-hi B plane [kp][n]
__device__ uint32_t g_bl[(size_t)512 * 2048];   // packed bf16-lo B plane
__device__ float g_asrc[NN * 6];
__device__ float g_adst[NN * 6];
__device__ float g_walpha[(size_t)NT * 6];      // unnormalized softmax weights (CSR order)
__device__ float g_adenom[NN * 6];
__device__ int   g_deg[NN];
__device__ int   g_row[NN + 1];
__device__ int   g_cursor[NN];
__device__ int   g_esrc[NT];
__device__ int   g_edst[NT];
__device__ int   g_csr_src[NT];
__device__ int   g_is64;

// ---------------- zero degrees + edge dtype detection (fused) ----------------
__global__ void zero_deg_kernel(const int* __restrict__ w) {
    int i = blockIdx.x * blockDim.x + threadIdx.x;
    if (i < NN) g_deg[i] = 0;
    if (i == 0) {
        int nz = 0;
        for (int k = 1; k < 2048; k += 2) nz += (w[k] != 0);
        g_is64 = (nz == 0) ? 1 : 0;
    }
}

__global__ void build_edges_kernel(const void* __restrict__ ei) {
    int t = blockIdx.x * blockDim.x + threadIdx.x;
    if (t >= NT) return;
    int s, d;
    if (t < NE) {
        if (g_is64) {
            const long long* p = (const long long*)ei;
            s = (int)p[t];
            d = (int)p[NE + t];
        } else {
            const int* p = (const int*)ei;
            s = p[t];
            d = p[NE + t];
        }
        s = min(max(s, 0), NN - 1);
        d = min(max(d, 0), NN - 1);
    } else {
        s = d = t - NE;  // self loop
    }
    g_esrc[t] = s;
    g_edst[t] = d;
    atomicAdd(&g_deg[d], 1);
}

// warp-shuffle hierarchical scan
__global__ void scan_kernel() {
    __shared__ int wsum[32];
    __shared__ int carry;
    int tid = threadIdx.x, lane = tid & 31, wid = tid >> 5;
    if (tid == 0) { carry = 0; g_row[0] = 0; }
    __syncthreads();
    for (int base = 0; base < NN; base += 1024) {
        int i = base + tid;
        int v = (i < NN) ? g_deg[i] : 0;
        int val = v;
#pragma unroll
        for (int off = 1; off < 32; off <<= 1) {
            int t = __shfl_up_sync(0xffffffffu, val, off);
            if (lane >= off) val += t;
        }
        if (lane == 31) wsum[wid] = val;
        __syncthreads();
        if (wid == 0) {
            int s = wsum[lane];
#pragma unroll
            for (int off = 1; off < 32; off <<= 1) {
                int t = __shfl_up_sync(0xffffffffu, s, off);
                if (lane >= off) s += t;
            }
            wsum[lane] = s;
        }
        __syncthreads();
        int prefix = carry + (wid > 0 ? wsum[wid - 1] : 0);
        int incl = prefix + val;
        if (i < NN) {
            g_row[i + 1] = incl;
            g_cursor[i]  = incl - v;
        }
        __syncthreads();
        if (tid == 0) carry += wsum[31];
        __syncthreads();
    }
}

__global__ void scatter_kernel() {
    int t = blockIdx.x * blockDim.x + threadIdx.x;
    if (t >= NT) return;
    int d = g_edst[t];
    int pos = atomicAdd(&g_cursor[d], 1);
    g_csr_src[pos] = g_esrc[t];
}

// ============================================================================
// hi/lo bf16 pre-conversion
// ============================================================================
__device__ __forceinline__ void packpair(float x0, float x1,
                                         uint32_t& hw, uint32_t& lw) {
    uint32_t b0 = __float_as_uint(x0), b1 = __float_as_uint(x1);
    uint32_t h0 = b0 & 0xFFFF0000u, h1 = b1 & 0xFFFF0000u;
    float l0 = x0 - __uint_as_float(h0);
    float l1 = x1 - __uint_as_float(h1);
    __nv_bfloat16 lb0 = __float2bfloat16(l0);
    __nv_bfloat16 lb1 = __float2bfloat16(l1);
    uint16_t u0 = *reinterpret_cast<uint16_t*>(&lb0);
    uint16_t u1 = *reinterpret_cast<uint16_t*>(&lb1);
    hw = (h0 >> 16) | h1;
    lw = (uint32_t)u0 | ((uint32_t)u1 << 16);
}

__global__ void cvt_a_kernel(const float* __restrict__ A, int M, int K,
                             int aStride) {
    int t = blockIdx.x * blockDim.x + threadIdx.x;
    if (t >= MPAD * aStride) return;
    int row = t / aStride, kp = t - row * aStride;
    float x0 = 0.f, x1 = 0.f;
    if (row < M) {
        int k0 = kp * 2;
        const float* ap = &A[(size_t)row * K];
        if (k0 < K)     x0 = ap[k0];
        if (k0 + 1 < K) x1 = ap[k0 + 1];
    }
    uint32_t hw, lw;
    packpair(x0, x1, hw, lw);
    g_ah[t] = hw;
    g_al[t] = lw;
}

__global__ void cvt_w_kernel(const float* __restrict__ B0, int N0c,
                             const float* __restrict__ B1, int N1c,
                             int K, int Np, int kpHalf) {
    int t = blockIdx.x * blockDim.x + threadIdx.x;
    if (t >= kpHalf * Np) return;
    int kp = t / Np, n = t - kp * Np;
    int k0 = kp * 2;
    float x0 = 0.f, x1 = 0.f;
    if (n < N0c) {
        if (k0 < K)     x0 = B0[(size_t)k0 * N0c + n];
        if (k0 + 1 < K) x1 = B0[(size_t)(k0 + 1) * N0c + n];
    } else if (B1 != nullptr && n - N0c < N1c) {
        int nn = n - N0c;
        if (k0 < K)     x0 = B1[(size_t)k0 * N1c + nn];
        if (k0 + 1 < K) x1 = B1[(size_t)(k0 + 1) * N1c + nn];
    }
    uint32_t hw, lw;
    packpair(x0, x1, hw, lw);
    g_bh[t] = hw;
    g_bl[t] = lw;
}

// ============================================================================
// bf16x3 tensor-core GEMM (R11-proven configuration)
// ============================================================================
#define AW  20
#define BW  136
#define A_P_STRIDE (128 * AW)
#define B_P_STRIDE (16 * BW)
#define BUF_WORDS  (2 * A_P_STRIDE + 2 * B_P_STRIDE)
#define GEMM_SMEM_BYTES (2 * BUF_WORDS * 4)

__device__ __forceinline__ void mma_bf16(float* c, const uint32_t* a,
                                         const uint32_t* b) {
    asm volatile(
        "mma.sync.aligned.m16n8k16.row.col.f32.bf16.bf16.f32 "
        "{%0,%1,%2,%3},{%4,%5,%6,%7},{%8,%9},{%0,%1,%2,%3};\n"
        : "+f"(c[0]), "+f"(c[1]), "+f"(c[2]), "+f"(c[3])
        : "r"(a[0]), "r"(a[1]), "r"(a[2]), "r"(a[3]), "r"(b[0]), "r"(b[1]));
}

__device__ __forceinline__ void cp16(uint32_t saddr, const void* g) {
    asm volatile("cp.async.cg.shared.global [%0], [%1], 16;\n"
                 :: "r"(saddr), "l"(g));
}

__global__ __launch_bounds__(256, 2) void mma_gemm_async(
    const uint32_t* __restrict__ Ah, const uint32_t* __restrict__ Al,
    const uint32_t* __restrict__ Bh, const uint32_t* __restrict__ Bl,
    float* __restrict__ C0, float* __restrict__ C1,
    int M, int aStride, int Np, int N0, int ld0, int N1, int ld1, int nkt) {
    extern __shared__ uint32_t sm[];
    const int tid  = threadIdx.x;
    const int warp = tid >> 5, lane = tid & 31;
    const int group = lane >> 2, tg = lane & 3;
    const int wM = (warp >> 2) * 64;
    const int wN = (warp & 3) * 32;
    const int tileM = blockIdx.y * 128;
    const int tileN = blockIdx.x * 128;

    const int aRow = tid >> 1, aHalf = tid & 1;
    const size_t aGbase = (size_t)(tileM + aRow) * aStride + aHalf * 8;
    const uint32_t aSbase = aRow * AW + aHalf * 8;
    const int bKp = tid >> 4, bN0 = (tid & 15) * 8;
    const uint32_t bSbase = bKp * BW + bN0;

    auto issue = [&](int kt, int buf) {
        uint32_t* s = sm + buf * BUF_WORDS;
        {
            const uint32_t* gh = Ah + aGbase + kt * 16;
            const uint32_t* gl = Al + aGbase + kt * 16;
            uint32_t sh_ = (uint32_t)__cvta_generic_to_shared(s + aSbase);
            uint32_t sl_ = (uint32_t)__cvta_generic_to_shared(s + A_P_STRIDE + aSbase);
            cp16(sh_, gh); cp16(sh_ + 16, gh + 4);
            cp16(sl_, gl); cp16(sl_ + 16, gl + 4);
        }
        {
            const size_t go = (size_t)(kt * 16 + bKp) * Np + tileN + bN0;
            const uint32_t* gh = Bh + go;
            const uint32_t* gl = Bl + go;
            uint32_t* bs = s + 2 * A_P_STRIDE;
            uint32_t sh_ = (uint32_t)__cvta_generic_to_shared(bs + bSbase);
            uint32_t sl_ = (uint32_t)__cvta_generic_to_shared(bs + B_P_STRIDE + bSbase);
            cp16(sh_, gh); cp16(sh_ + 16, gh + 4);
            cp16(sl_, gl); cp16(sl_ + 16, gl + 4);
        }
    };

    float acc[4][4][4] = {};

    issue(0, 0);
    asm volatile("cp.async.commit_group;\n");

    for (int t = 0; t < nkt; t++) {
        const int cur = t & 1;
        const bool more = (t + 1 < nkt);
        if (more) {
            issue(t + 1, cur ^ 1);
            asm volatile("cp.async.commit_group;\n");
            asm volatile("cp.async.wait_group 1;\n");
        } else {
            asm volatile("cp.async.wait_group 0;\n");
        }
        __syncthreads();

        const uint32_t* As_ = sm + cur * BUF_WORDS;
        const uint32_t* Bs_ = sm + cur * BUF_WORDS + 2 * A_P_STRIDE;
#pragma unroll
        for (int ks = 0; ks < 2; ks++) {
            const int kb2 = ks * 8;
            uint32_t afr[4][2][4];
#pragma unroll
            for (int i = 0; i < 4; i++) {
                int row = wM + i * 16 + group;
#pragma unroll
                for (int p = 0; p < 2; p++) {
                    const uint32_t* Ap = As_ + p * A_P_STRIDE;
                    afr[i][p][0] = Ap[row * AW + kb2 + tg];
                    afr[i][p][1] = Ap[(row + 8) * AW + kb2 + tg];
                    afr[i][p][2] = Ap[row * AW + kb2 + 4 + tg];
                    afr[i][p][3] = Ap[(row + 8) * AW + kb2 + 4 + tg];
                }
            }
            uint32_t bfr[4][2][2];
#pragma unroll
            for (int j = 0; j < 4; j++) {
                int n = wN + j * 8 + group;
#pragma unroll
                for (int p = 0; p < 2; p++) {
                    const uint32_t* Bp = Bs_ + p * B_P_STRIDE;
                    bfr[j][p][0] = Bp[(kb2 + tg) * BW + n];
                    bfr[j][p][1] = Bp[(kb2 + 4 + tg) * BW + n];
                }
            }
#pragma unroll
            for (int i = 0; i < 4; i++)
#pragma unroll
                for (int j = 0; j < 4; j++)
                    mma_bf16(acc[i][j], afr[i][0], bfr[j][0]);  // hi*hi
#pragma unroll
            for (int i = 0; i < 4; i++)
#pragma unroll
                for (int j = 0; j < 4; j++)
                    mma_bf16(acc[i][j], afr[i][0], bfr[j][1]);  // hi*lo
#pragma unroll
            for (int i = 0; i < 4; i++)
#pragma unroll
                for (int j = 0; j < 4; j++)
                    mma_bf16(acc[i][j], afr[i][1], bfr[j][0]);  // lo*hi
        }
        __syncthreads();
    }

    auto store = [&](int gm, int gn, float v) {
        if (gm >= M) return;
        if (gn < N0) {
            C0[(size_t)gm * ld0 + gn] = v;
        } else {
            int n2 = gn - N0;
            if (n2 < N1) C1[(size_t)gm * ld1 + n2] = v;
        }
    };
#pragma unroll
    for (int i = 0; i < 4; i++) {
        int row0 = tileM + wM + i * 16 + group;
#pragma unroll
        for (int j = 0; j < 4; j++) {
            int col0 = tileN + wN + j * 8 + tg * 2;
            store(row0,     col0,     acc[i][j][0]);
            store(row0,     col0 + 1, acc[i][j][1]);
            store(row0 + 8, col0,     acc[i][j][2]);
            store(row0 + 8, col0 + 1, acc[i][j][3]);
        }
    }
}

// ---------------- per-node attention logits ---------------------------------
__global__ void compute_alpha_kernel(const float* __restrict__ xl,
                                     const float* __restrict__ a_src,
                                     const float* __restrict__ a_dst,
                                     int H, int C, int LD) {
    int n = blockIdx.x;
    int h = threadIdx.x >> 5;
    int lane = threadIdx.x & 31;
    const float* xr = xl + (size_t)n * LD + h * C;
    float ss = 0.f, sd = 0.f;
    for (int c = lane; c < C; c += 32) {
        float v = xr[c];
        ss += v * a_src[h * C + c];
        sd += v * a_dst[h * C + c];
    }
#pragma unroll
    for (int off = 16; off > 0; off >>= 1) {
        ss += __shfl_down_sync(0xffffffffu, ss, off);
        sd += __shfl_down_sync(0xffffffffu, sd, off);
    }
    if (lane == 0) {
        g_asrc[n * H + h] = ss;
        g_adst[n * H + h] = sd;
    }
}

// ---------------- edge softmax: weights + denominator (CSR order) ------------
__global__ void edge_softmax_kernel(int H) {
    int d = blockIdx.x;
    int h = threadIdx.x >> 5;
    int lane = threadIdx.x & 31;
    int r0 = g_row[d], r1 = g_row[d + 1];
    float adv = g_adst[d * H + h];

    float mx = -1e30f;
    for (int j = r0 + lane; j < r1; j += 32)
        mx = fmaxf(mx, g_asrc[g_csr_src[j] * H + h]);
#pragma unroll
    for (int off = 16; off > 0; off >>= 1)
        mx = fmaxf(mx, __shfl_xor_sync(0xffffffffu, mx, off));
    float m = mx + adv;
    m = (m > 0.f) ? m : 0.2f * m;  // leaky relu commutes with max (monotonic)

    float sum = 0.f;
    for (int j = r0 + lane; j < r1; j += 32) {
        float e = g_asrc[g_csr_src[j] * H + h] + adv;
        e = (e > 0.f) ? e : 0.2f * e;
        float w = __expf(e - m);
        g_walpha[(size_t)j * H + h] = w;
        sum += w;
    }
#pragma unroll
    for (int off = 16; off > 0; off >>= 1)
        sum += __shfl_xor_sync(0xffffffffu, sum, off);
    if (lane == 0) g_adenom[d * H + h] = sum;
}

// ---------------- gather (layers 1,2): ALIGNED, MLP=8 ------------------------
__global__ void gat_gather_kernel(const float* __restrict__ xl,
                                  float* __restrict__ out,
                                  int H, int C, int LD) {
    int d = blockIdx.x;
    int tid = threadIdx.x;
    int f = tid * 4;
    int r0 = g_row[d], r1 = g_row[d + 1];
    int h0 = f / C;

    float4 acc = make_float4(0.f, 0.f, 0.f, 0.f);
    int j = r0;
    for (; j + 7 < r1; j += 8) {
        int s[8];
        float w[8];
        float4 v[8];
#pragma unroll
        for (int q = 0; q < 8; q++) s[q] = g_csr_src[j + q];
#pragma unroll
        for (int q = 0; q < 8; q++) w[q] = g_walpha[(size_t)(j + q) * H + h0];
#pragma unroll
        for (int q = 0; q < 8; q++)
            v[q] = *(reinterpret_cast<const float4*>(xl + (size_t)s[q] * LD) + tid);
#pragma unroll
        for (int q = 0; q < 8; q++) {
            acc.x += w[q] * v[q].x;
            acc.y += w[q] * v[q].y;
            acc.z += w[q] * v[q].z;
            acc.w += w[q] * v[q].w;
        }
    }
    for (; j + 3 < r1; j += 4) {
        int s[4];
        float w[4];
        float4 v[4];
#pragma unroll
        for (int q = 0; q < 4; q++) s[q] = g_csr_src[j + q];
#pragma unroll
        for (int q = 0; q < 4; q++) w[q] = g_walpha[(size_t)(j + q) * H + h0];
#pragma unroll
        for (int q = 0; q < 4; q++)
            v[q] = *(reinterpret_cast<const float4*>(xl + (size_t)s[q] * LD) + tid);
#pragma unroll
        for (int q = 0; q < 4; q++) {
            acc.x += w[q] * v[q].x;
            acc.y += w[q] * v[q].y;
            acc.z += w[q] * v[q].z;
            acc.w += w[q] * v[q].w;
        }
    }
    for (; j < r1; j++) {
        int s0 = g_csr_src[j];
        float w0 = g_walpha[(size_t)j * H + h0];
        float4 v0 = *(reinterpret_cast<const float4*>(xl + (size_t)s0 * LD) + tid);
        acc.x += w0 * v0.x;
        acc.y += w0 * v0.y;
        acc.z += w0 * v0.z;
        acc.w += w0 * v0.w;
    }

    float inv = 1.f / (g_adenom[d * H + h0] + 1e-16f);
    float4 r = make_float4(acc.x * inv, acc.y * inv, acc.z * inv, acc.w * inv);
    *(reinterpret_cast<float4*>(out + (size_t)d * LD + f)) = r;
}

// ---------------- layer-3 gather + head-mean fused ---------------------------
// H=6, C=121, HC=726; xl row stride LD=728. Writes out[d*121 + c] directly.
__global__ void gat_gather_mean_kernel(const float* __restrict__ xl,
                                       const float* __restrict__ b3,
                                       float* __restrict__ out) {
    const int H = 6, C = 121, HC = 726, LD = 728;
    __shared__ float sv[728];
    int d = blockIdx.x;
    int tid = threadIdx.x;     // 192 threads
    int f = tid * 4;
    int r0 = g_row[d], r1 = g_row[d + 1];

    bool active = (f < HC);
    int h0 = min(f / C, H - 1);
    int h1 = min((f + 1) / C, H - 1);
    int h2 = min((f + 2) / C, H - 1);
    int h3 = min((f + 3) / C, H - 1);

    float4 acc = make_float4(0.f, 0.f, 0.f, 0.f);
    if (active) {
        int j = r0;
        for (; j + 3 < r1; j += 4) {
            int s[4];
            const float* wp[4];
            float4 v[4];
#pragma unroll
            for (int q = 0; q < 4; q++) s[q] = g_csr_src[j + q];
#pragma unroll
            for (int q = 0; q < 4; q++) wp[q] = &g_walpha[(size_t)(j + q) * H];
#pragma unroll
            for (int q = 0; q < 4; q++)
                v[q] = *(reinterpret_cast<const float4*>(xl + (size_t)s[q] * LD) + tid);
#pragma unroll
            for (int q = 0; q < 4; q++) {
                acc.x += wp[q][h0] * v[q].x;
                acc.y += wp[q][h1] * v[q].y;
                acc.z += wp[q][h2] * v[q].z;
                acc.w += wp[q][h3] * v[q].w;
            }
        }
        for (; j < r1; j++) {
            int s0 = g_csr_src[j];
            const float* wp0 = &g_walpha[(size_t)j * H];
            float4 v0 = *(reinterpret_cast<const float4*>(xl + (size_t)s0 * LD) + tid);
            acc.x += wp0[h0] * v0.x;
            acc.y += wp0[h1] * v0.y;
            acc.z += wp0[h2] * v0.z;
            acc.w += wp0[h3] * v0.w;
        }
    }

    const float* dn = &g_adenom[d * H];
    if (active) {
        sv[f]     = acc.x / (dn[h0] + 1e-16f);
        if (f + 1 < HC) sv[f + 1] = acc.y / (dn[h1] + 1e-16f);
        if (f + 2 < HC) sv[f + 2] = acc.z / (dn[h2] + 1e-16f);
        if (f + 3 < HC) sv[f + 3] = acc.w / (dn[h3] + 1e-16f);
    }
    __syncthreads();
    if (tid < C) {
        float s = 0.f;
#pragma unroll
        for (int h = 0; h < 6; h++) s += sv[h * C + tid];
        out[(size_t)d * C + tid] = s * (1.f / 6.f) + b3[tid];
    }
}

// ---------------- fused add-skip + layernorm + elu -> packed bf16 planes -----
__global__ __launch_bounds__(256) void ln_elu_pack_kernel(
    const float* __restrict__ agg, const float* __restrict__ b,
    const float* __restrict__ skip, const float* __restrict__ skipb,
    const float* __restrict__ g, const float* __restrict__ beta) {
    int row = blockIdx.x;
    int tid = threadIdx.x;
    const size_t base = (size_t)row * 1024;
    int f = tid * 4;
    float4 a4 = *(const float4*)(agg + base + f);
    float4 s4 = *(const float4*)(skip + base + f);
    float4 b4 = *(const float4*)(b + f);
    float4 sb4 = *(const float4*)(skipb + f);
    float pre[4] = {a4.x + s4.x + b4.x + sb4.x, a4.y + s4.y + b4.y + sb4.y,
                    a4.z + s4.z + b4.z + sb4.z, a4.w + s4.w + b4.w + sb4.w};
    float sum = pre[0] + pre[1] + pre[2] + pre[3];
    __shared__ float red[256];
    red[tid] = sum;
    __syncthreads();
    for (int s = 128; s > 0; s >>= 1) {
        if (tid < s) red[tid] += red[tid + s];
        __syncthreads();
    }
    float mu = red[0] * (1.f / 1024.f);
    __syncthreads();
    float sq = 0.f;
#pragma unroll
    for (int k = 0; k < 4; k++) {
        float dlt = pre[k] - mu;
        sq += dlt * dlt;
    }
    red[tid] = sq;
    __syncthreads();
    for (int s = 128; s > 0; s >>= 1) {
        if (tid < s) red[tid] += red[tid + s];
        __syncthreads();
    }
    float rstd = rsqrtf(red[0] * (1.f / 1024.f) + 1e-5f);
    float4 g4 = *(const float4*)(g + f);
    float4 be4 = *(const float4*)(beta + f);
    float y[4];
    y[0] = (pre[0] - mu) * rstd * g4.x + be4.x;
    y[1] = (pre[1] - mu) * rstd * g4.y + be4.y;
    y[2] = (pre[2] - mu) * rstd * g4.z + be4.z;
    y[3] = (pre[3] - mu) * rstd * g4.w + be4.w;
#pragma unroll
    for (int k = 0; k < 4; k++) y[k] = (y[k] > 0.f) ? y[k] : expm1f(y[k]);
    uint32_t hw0, lw0, hw1, lw1;
    packpair(y[0], y[1], hw0, lw0);
    packpair(y[2], y[3], hw1, lw1);
    size_t w = (size_t)row * 512 + 2 * tid;
    g_ah[w] = hw0; g_ah[w + 1] = hw1;
    g_al[w] = lw0; g_al[w + 1] = lw1;
}

// ---------------- host orchestration -----------------------------------------
extern "C" void kernel_launch(void* const* d_in, const int* in_sizes, int n_in,
                              void* d_out, int out_size) {
    const float* x      = (const float*)d_in[0];
    const void*  ei     = d_in[1];
    const float* W1     = (const float*)d_in[2];
    const float* a_src1 = (const float*)d_in[3];
    const float* a_dst1 = (const float*)d_in[4];
    const float* b1     = (const float*)d_in[5];
    const float* W2     = (const float*)d_in[6];
    const float* a_src2 = (const float*)d_in[7];
    const float* a_dst2 = (const float*)d_in[8];
    const float* b2     = (const float*)d_in[9];
    const float* W3     = (const float*)d_in[10];
    const float* a_src3 = (const float*)d_in[11];
    const float* a_dst3 = (const float*)d_in[12];
    const float* b3     = (const float*)d_in[13];
    const float* skipW1 = (const float*)d_in[14];
    const float* skipb1 = (const float*)d_in[15];
    const float* skipW2 = (const float*)d_in[16];
    const float* skipb2 = (const float*)d_in[17];
    const float* g1     = (const float*)d_in[18];
    const float* beta1  = (const float*)d_in[19];
    const float* g2     = (const float*)d_in[20];
    const float* beta2  = (const float*)d_in[21];
    float* out = (float*)d_out;

    float *p_xl, *p_skip, *p_agg;
    uint32_t *p_ah, *p_al, *p_bh, *p_bl;
    cudaGetSymbolAddress((void**)&p_xl, g_xl);
    cudaGetSymbolAddress((void**)&p_skip, g_skip);
    cudaGetSymbolAddress((void**)&p_agg, g_agg);
    cudaGetSymbolAddress((void**)&p_ah, g_ah);
    cudaGetSymbolAddress((void**)&p_al, g_al);
    cudaGetSymbolAddress((void**)&p_bh, g_bh);
    cudaGetSymbolAddress((void**)&p_bl, g_bl);

    cudaFuncSetAttribute(mma_gemm_async,
                         cudaFuncAttributeMaxDynamicSharedMemorySize,
                         GEMM_SMEM_BYTES);

    // ---- CSR build (edges shared by all 3 layers) ----
    zero_deg_kernel<<<(NN + 255) / 256, 256>>>((const int*)ei);
    build_edges_kernel<<<(NT + 255) / 256, 256>>>(ei);
    scan_kernel<<<1, 1024>>>();
    scatter_kernel<<<(NT + 255) / 256, 256>>>();

    const int gridM = MPAD / 128;   // 157

    // ---- Layer 1: GATConv(50 -> 256, H=4, concat) + skip; K=50 Kpad=64 ----
    {
        const int K = 50, aStride = 32, nkt = 2, Np = 2048;
        cvt_w_kernel<<<((Np * aStride) + 255) / 256, 256>>>(
            W1, 1024, skipW1, 1024, K, Np, aStride);
        cvt_a_kernel<<<((MPAD * aStride) + 255) / 256, 256>>>(x, NN, K, aStride);
        mma_gemm_async<<<dim3(16, gridM), 256, GEMM_SMEM_BYTES>>>(
            p_ah, p_al, p_bh, p_bl, p_xl, p_skip, NN, aStride, Np,
            1024, 1024, 1024, 1024, nkt);
    }
    compute_alpha_kernel<<<NN, 4 * 32>>>(p_xl, a_src1, a_dst1, 4, 256, 1024);
    edge_softmax_kernel<<<NN, 4 * 32>>>(4);
    gat_gather_kernel<<<NN, 256>>>(p_xl, p_agg, 4, 256, 1024);
    ln_elu_pack_kernel<<<NN, 256>>>(p_agg, b1, p_skip, skipb1, g1, beta1);

    // ---- Layer 2: GATConv(1024 -> 256, H=4, concat) + skip ----
    {
        const int aStride = 512, nkt = 32, Np = 2048;
        cvt_w_kernel<<<((Np * aStride) + 255) / 256, 256>>>(
            W2, 1024, skipW2, 1024, 1024, Np, aStride);
        mma_gemm_async<<<dim3(16, gridM), 256, GEMM_SMEM_BYTES>>>(
            p_ah, p_al, p_bh, p_bl, p_xl, p_skip, NN, aStride, Np,
            1024, 1024, 1024, 1024, nkt);
    }
    compute_alpha_kernel<<<NN, 4 * 32>>>(p_xl, a_src2, a_dst2, 4, 256, 1024);
    edge_softmax_kernel<<<NN, 4 * 32>>>(4);
    gat_gather_kernel<<<NN, 256>>>(p_xl, p_agg, 4, 256, 1024);
    ln_elu_pack_kernel<<<NN, 256>>>(p_agg, b2, p_skip, skipb2, g2, beta2);

    // ---- Layer 3: GATConv(1024 -> 121, H=6, mean); N=726, row stride 728 ----
    {
        const int aStride = 512, nkt = 32, Np = 768;
        cvt_w_kernel<<<((Np * aStride) + 255) / 256, 256>>>(
            W3, 726, (const float*)nullptr, 0, 1024, Np, aStride);
        mma_gemm_async<<<dim3(6, gridM), 256, GEMM_SMEM_BYTES>>>(
            p_ah, p_al, p_bh, p_bl, p_xl, p_xl, NN, aStride, Np,
            726, 728, 0, 728, nkt);
    }
    compute_alpha_kernel<<<NN, 6 * 32>>>(p_xl, a_src3, a_dst3, 6, 121, 728);
    edge_softmax_kernel<<<NN, 6 * 32>>>(6);
    gat_gather_mean_kernel<<<NN, 192>>>(p_xl, b3, out);
}

// round 16
// speedup vs baseline: 1.0771x; 1.0360x over previous
#include <cuda_runtime.h>
#include <cuda_bf16.h>
#include <cstdint>

#define NN 20000
#define MPAD 20096              // NN rounded up to 128
#define NE 320000
#define NT (NE + NN)

// ---------------- scratch (device globals; no allocations allowed) ----------
__device__ float g_xl[(size_t)NN * 1024];
__device__ float g_skip[(size_t)NN * 1024];
__device__ uint32_t g_ah[(size_t)MPAD * 512];   // packed bf16-hi A plane
__device__ uint32_t g_al[(size_t)MPAD * 512];   // packed bf16-lo A plane
__device__ uint32_t g_bh[(size_t)512 * 2048];   // packed bf16-hi B plane [kp][n]
__device__ uint32_t g_bl[(size_t)512 * 2048];   // packed bf16-lo B plane
__device__ float g_asrc[NN * 6];
__device__ float g_adst[NN * 6];
__device__ float g_walpha[(size_t)NT * 6];      // unnormalized softmax weights (CSR order)
__device__ float g_adenom[NN * 6];
__device__ int   g_deg[NN];
__device__ int   g_row[NN + 1];
__device__ int   g_cursor[NN];
__device__ int   g_esrc[NT];
__device__ int   g_edst[NT];
__device__ int   g_csr_src[NT];
__device__ int   g_is64;

// ---------------- zero degrees + edge dtype detection (fused) ----------------
__global__ void zero_deg_kernel(const int* __restrict__ w) {
    int i = blockIdx.x * blockDim.x + threadIdx.x;
    if (i < NN) g_deg[i] = 0;
    if (i == 0) {
        int nz = 0;
        for (int k = 1; k < 2048; k += 2) nz += (w[k] != 0);
        g_is64 = (nz == 0) ? 1 : 0;
    }
}

__global__ void build_edges_kernel(const void* __restrict__ ei) {
    int t = blockIdx.x * blockDim.x + threadIdx.x;
    if (t >= NT) return;
    int s, d;
    if (t < NE) {
        if (g_is64) {
            const long long* p = (const long long*)ei;
            s = (int)p[t];
            d = (int)p[NE + t];
        } else {
            const int* p = (const int*)ei;
            s = p[t];
            d = p[NE + t];
        }
        s = min(max(s, 0), NN - 1);
        d = min(max(d, 0), NN - 1);
    } else {
        s = d = t - NE;  // self loop
    }
    g_esrc[t] = s;
    g_edst[t] = d;
    atomicAdd(&g_deg[d], 1);
}

// warp-shuffle hierarchical scan
__global__ void scan_kernel() {
    __shared__ int wsum[32];
    __shared__ int carry;
    int tid = threadIdx.x, lane = tid & 31, wid = tid >> 5;
    if (tid == 0) { carry = 0; g_row[0] = 0; }
    __syncthreads();
    for (int base = 0; base < NN; base += 1024) {
        int i = base + tid;
        int v = (i < NN) ? g_deg[i] : 0;
        int val = v;
#pragma unroll
        for (int off = 1; off < 32; off <<= 1) {
            int t = __shfl_up_sync(0xffffffffu, val, off);
            if (lane >= off) val += t;
        }
        if (lane == 31) wsum[wid] = val;
        __syncthreads();
        if (wid == 0) {
            int s = wsum[lane];
#pragma unroll
            for (int off = 1; off < 32; off <<= 1) {
                int t = __shfl_up_sync(0xffffffffu, s, off);
                if (lane >= off) s += t;
            }
            wsum[lane] = s;
        }
        __syncthreads();
        int prefix = carry + (wid > 0 ? wsum[wid - 1] : 0);
        int incl = prefix + val;
        if (i < NN) {
            g_row[i + 1] = incl;
            g_cursor[i]  = incl - v;
        }
        __syncthreads();
        if (tid == 0) carry += wsum[31];
        __syncthreads();
    }
}

__global__ void scatter_kernel() {
    int t = blockIdx.x * blockDim.x + threadIdx.x;
    if (t >= NT) return;
    int d = g_edst[t];
    int pos = atomicAdd(&g_cursor[d], 1);
    g_csr_src[pos] = g_esrc[t];
}

// ============================================================================
// hi/lo bf16 pre-conversion  (zeroAlphaN > 0 -> also zero g_asrc/g_adst[0..N))
// ============================================================================
__device__ __forceinline__ void packpair(float x0, float x1,
                                         uint32_t& hw, uint32_t& lw) {
    uint32_t b0 = __float_as_uint(x0), b1 = __float_as_uint(x1);
    uint32_t h0 = b0 & 0xFFFF0000u, h1 = b1 & 0xFFFF0000u;
    float l0 = x0 - __uint_as_float(h0);
    float l1 = x1 - __uint_as_float(h1);
    __nv_bfloat16 lb0 = __float2bfloat16(l0);
    __nv_bfloat16 lb1 = __float2bfloat16(l1);
    uint16_t u0 = *reinterpret_cast<uint16_t*>(&lb0);
    uint16_t u1 = *reinterpret_cast<uint16_t*>(&lb1);
    hw = (h0 >> 16) | h1;
    lw = (uint32_t)u0 | ((uint32_t)u1 << 16);
}

__global__ void cvt_a_kernel(const float* __restrict__ A, int M, int K,
                             int aStride, int zeroAlphaN) {
    int t = blockIdx.x * blockDim.x + threadIdx.x;
    if (t < zeroAlphaN) { g_asrc[t] = 0.f; g_adst[t] = 0.f; }
    if (t >= MPAD * aStride) return;
    int row = t / aStride, kp = t - row * aStride;
    float x0 = 0.f, x1 = 0.f;
    if (row < M) {
        int k0 = kp * 2;
        const float* ap = &A[(size_t)row * K];
        if (k0 < K)     x0 = ap[k0];
        if (k0 + 1 < K) x1 = ap[k0 + 1];
    }
    uint32_t hw, lw;
    packpair(x0, x1, hw, lw);
    g_ah[t] = hw;
    g_al[t] = lw;
}

__global__ void cvt_w_kernel(const float* __restrict__ B0, int N0c,
                             const float* __restrict__ B1, int N1c,
                             int K, int Np, int kpHalf, int zeroAlphaN) {
    int t = blockIdx.x * blockDim.x + threadIdx.x;
    if (t < zeroAlphaN) { g_asrc[t] = 0.f; g_adst[t] = 0.f; }
    if (t >= kpHalf * Np) return;
    int kp = t / Np, n = t - kp * Np;
    int k0 = kp * 2;
    float x0 = 0.f, x1 = 0.f;
    if (n < N0c) {
        if (k0 < K)     x0 = B0[(size_t)k0 * N0c + n];
        if (k0 + 1 < K) x1 = B0[(size_t)(k0 + 1) * N0c + n];
    } else if (B1 != nullptr && n - N0c < N1c) {
        int nn = n - N0c;
        if (k0 < K)     x0 = B1[(size_t)k0 * N1c + nn];
        if (k0 + 1 < K) x1 = B1[(size_t)(k0 + 1) * N1c + nn];
    }
    uint32_t hw, lw;
    packpair(x0, x1, hw, lw);
    g_bh[t] = hw;
    g_bl[t] = lw;
}

// ============================================================================
// bf16x3 tensor-core GEMM (R11-proven mainloop) + fused alpha epilogue.
// If avec != nullptr: for output cols < N0 (xl part), accumulate per-(row,head)
// partial dots with avec/advec into g_asrc/g_adst via atomics.
// Requires Calpha % 32 == 0 (warp band within one head).
// ============================================================================
#define AW  20
#define BW  136
#define A_P_STRIDE (128 * AW)
#define B_P_STRIDE (16 * BW)
#define BUF_WORDS  (2 * A_P_STRIDE + 2 * B_P_STRIDE)
#define GEMM_SMEM_BYTES (2 * BUF_WORDS * 4)

__device__ __forceinline__ void mma_bf16(float* c, const uint32_t* a,
                                         const uint32_t* b) {
    asm volatile(
        "mma.sync.aligned.m16n8k16.row.col.f32.bf16.bf16.f32 "
        "{%0,%1,%2,%3},{%4,%5,%6,%7},{%8,%9},{%0,%1,%2,%3};\n"
        : "+f"(c[0]), "+f"(c[1]), "+f"(c[2]), "+f"(c[3])
        : "r"(a[0]), "r"(a[1]), "r"(a[2]), "r"(a[3]), "r"(b[0]), "r"(b[1]));
}

__device__ __forceinline__ void cp16(uint32_t saddr, const void* g) {
    asm volatile("cp.async.cg.shared.global [%0], [%1], 16;\n"
                 :: "r"(saddr), "l"(g));
}

__global__ __launch_bounds__(256, 2) void mma_gemm_async(
    const uint32_t* __restrict__ Ah, const uint32_t* __restrict__ Al,
    const uint32_t* __restrict__ Bh, const uint32_t* __restrict__ Bl,
    float* __restrict__ C0, float* __restrict__ C1,
    int M, int aStride, int Np, int N0, int ld0, int N1, int ld1, int nkt,
    const float* __restrict__ avec, const float* __restrict__ advec,
    int Halpha, int Calpha) {
    extern __shared__ uint32_t sm[];
    const int tid  = threadIdx.x;
    const int warp = tid >> 5, lane = tid & 31;
    const int group = lane >> 2, tg = lane & 3;
    const int wM = (warp >> 2) * 64;
    const int wN = (warp & 3) * 32;
    const int tileM = blockIdx.y * 128;
    const int tileN = blockIdx.x * 128;

    const int aRow = tid >> 1, aHalf = tid & 1;
    const size_t aGbase = (size_t)(tileM + aRow) * aStride + aHalf * 8;
    const uint32_t aSbase = aRow * AW + aHalf * 8;
    const int bKp = tid >> 4, bN0 = (tid & 15) * 8;
    const uint32_t bSbase = bKp * BW + bN0;

    auto issue = [&](int kt, int buf) {
        uint32_t* s = sm + buf * BUF_WORDS;
        {
            const uint32_t* gh = Ah + aGbase + kt * 16;
            const uint32_t* gl = Al + aGbase + kt * 16;
            uint32_t sh_ = (uint32_t)__cvta_generic_to_shared(s + aSbase);
            uint32_t sl_ = (uint32_t)__cvta_generic_to_shared(s + A_P_STRIDE + aSbase);
            cp16(sh_, gh); cp16(sh_ + 16, gh + 4);
            cp16(sl_, gl); cp16(sl_ + 16, gl + 4);
        }
        {
            const size_t go = (size_t)(kt * 16 + bKp) * Np + tileN + bN0;
            const uint32_t* gh = Bh + go;
            const uint32_t* gl = Bl + go;
            uint32_t* bs = s + 2 * A_P_STRIDE;
            uint32_t sh_ = (uint32_t)__cvta_generic_to_shared(bs + bSbase);
            uint32_t sl_ = (uint32_t)__cvta_generic_to_shared(bs + B_P_STRIDE + bSbase);
            cp16(sh_, gh); cp16(sh_ + 16, gh + 4);
            cp16(sl_, gl); cp16(sl_ + 16, gl + 4);
        }
    };

    float acc[4][4][4] = {};

    issue(0, 0);
    asm volatile("cp.async.commit_group;\n");

    for (int t = 0; t < nkt; t++) {
        const int cur = t & 1;
        const bool more = (t + 1 < nkt);
        if (more) {
            issue(t + 1, cur ^ 1);
            asm volatile("cp.async.commit_group;\n");
            asm volatile("cp.async.wait_group 1;\n");
        } else {
            asm volatile("cp.async.wait_group 0;\n");
        }
        __syncthreads();

        const uint32_t* As_ = sm + cur * BUF_WORDS;
        const uint32_t* Bs_ = sm + cur * BUF_WORDS + 2 * A_P_STRIDE;
#pragma unroll
        for (int ks = 0; ks < 2; ks++) {
            const int kb2 = ks * 8;
            uint32_t afr[4][2][4];
#pragma unroll
            for (int i = 0; i < 4; i++) {
                int row = wM + i * 16 + group;
#pragma unroll
                for (int p = 0; p < 2; p++) {
                    const uint32_t* Ap = As_ + p * A_P_STRIDE;
                    afr[i][p][0] = Ap[row * AW + kb2 + tg];
                    afr[i][p][1] = Ap[(row + 8) * AW + kb2 + tg];
                    afr[i][p][2] = Ap[row * AW + kb2 + 4 + tg];
                    afr[i][p][3] = Ap[(row + 8) * AW + kb2 + 4 + tg];
                }
            }
            uint32_t bfr[4][2][2];
#pragma unroll
            for (int j = 0; j < 4; j++) {
                int n = wN + j * 8 + group;
#pragma unroll
                for (int p = 0; p < 2; p++) {
                    const uint32_t* Bp = Bs_ + p * B_P_STRIDE;
                    bfr[j][p][0] = Bp[(kb2 + tg) * BW + n];
                    bfr[j][p][1] = Bp[(kb2 + 4 + tg) * BW + n];
                }
            }
#pragma unroll
            for (int i = 0; i < 4; i++)
#pragma unroll
                for (int j = 0; j < 4; j++)
                    mma_bf16(acc[i][j], afr[i][0], bfr[j][0]);  // hi*hi
#pragma unroll
            for (int i = 0; i < 4; i++)
#pragma unroll
                for (int j = 0; j < 4; j++)
                    mma_bf16(acc[i][j], afr[i][0], bfr[j][1]);  // hi*lo
#pragma unroll
            for (int i = 0; i < 4; i++)
#pragma unroll
                for (int j = 0; j < 4; j++)
                    mma_bf16(acc[i][j], afr[i][1], bfr[j][0]);  // lo*hi
        }
        __syncthreads();
    }

    // ---------------- epilogue: store + optional fused alpha ----------------
    auto store = [&](int gm, int gn, float v) {
        if (gm >= M) return;
        if (gn < N0) {
            C0[(size_t)gm * ld0 + gn] = v;
        } else {
            int n2 = gn - N0;
            if (n2 < N1) C1[(size_t)gm * ld1 + n2] = v;
        }
    };
#pragma unroll
    for (int i = 0; i < 4; i++) {
        int row0 = tileM + wM + i * 16 + group;
#pragma unroll
        for (int j = 0; j < 4; j++) {
            int col0 = tileN + wN + j * 8 + tg * 2;
            store(row0,     col0,     acc[i][j][0]);
            store(row0,     col0 + 1, acc[i][j][1]);
            store(row0 + 8, col0,     acc[i][j][2]);
            store(row0 + 8, col0 + 1, acc[i][j][3]);
        }
    }

    if (avec != nullptr && (tileN + wN) < N0) {
        const int head = (tileN + wN) / Calpha;
#pragma unroll
        for (int i = 0; i < 4; i++) {
            float s0s = 0.f, s0d = 0.f, s1s = 0.f, s1d = 0.f;
#pragma unroll
            for (int j = 0; j < 4; j++) {
                int c0 = tileN + wN + j * 8 + tg * 2;
                float av0 = avec[c0], av1 = avec[c0 + 1];
                float ad0 = advec[c0], ad1 = advec[c0 + 1];
                s0s += acc[i][j][0] * av0 + acc[i][j][1] * av1;
                s0d += acc[i][j][0] * ad0 + acc[i][j][1] * ad1;
                s1s += acc[i][j][2] * av0 + acc[i][j][3] * av1;
                s1d += acc[i][j][2] * ad0 + acc[i][j][3] * ad1;
            }
#pragma unroll
            for (int off = 1; off < 4; off <<= 1) {
                s0s += __shfl_xor_sync(0xffffffffu, s0s, off);
                s0d += __shfl_xor_sync(0xffffffffu, s0d, off);
                s1s += __shfl_xor_sync(0xffffffffu, s1s, off);
                s1d += __shfl_xor_sync(0xffffffffu, s1d, off);
            }
            if (tg == 0) {
                int r0 = tileM + wM + i * 16 + group;
                if (r0 < M) {
                    atomicAdd(&g_asrc[r0 * Halpha + head], s0s);
                    atomicAdd(&g_adst[r0 * Halpha + head], s0d);
                }
                if (r0 + 8 < M) {
                    atomicAdd(&g_asrc[(r0 + 8) * Halpha + head], s1s);
                    atomicAdd(&g_adst[(r0 + 8) * Halpha + head], s1d);
                }
            }
        }
    }
}

// ---------------- per-node attention logits (layer 3 only) -------------------
__global__ void compute_alpha_kernel(const float* __restrict__ xl,
                                     const float* __restrict__ a_src,
                                     const float* __restrict__ a_dst,
                                     int H, int C, int LD) {
    int n = blockIdx.x;
    int h = threadIdx.x >> 5;
    int lane = threadIdx.x & 31;
    const float* xr = xl + (size_t)n * LD + h * C;
    float ss = 0.f, sd = 0.f;
    for (int c = lane; c < C; c += 32) {
        float v = xr[c];
        ss += v * a_src[h * C + c];
        sd += v * a_dst[h * C + c];
    }
#pragma unroll
    for (int off = 16; off > 0; off >>= 1) {
        ss += __shfl_down_sync(0xffffffffu, ss, off);
        sd += __shfl_down_sync(0xffffffffu, sd, off);
    }
    if (lane == 0) {
        g_asrc[n * H + h] = ss;
        g_adst[n * H + h] = sd;
    }
}

// ---------------- edge softmax: weights + denominator (CSR order) ------------
__global__ void edge_softmax_kernel(int H) {
    int d = blockIdx.x;
    int h = threadIdx.x >> 5;
    int lane = threadIdx.x & 31;
    int r0 = g_row[d], r1 = g_row[d + 1];
    float adv = g_adst[d * H + h];

    float mx = -1e30f;
    for (int j = r0 + lane; j < r1; j += 32)
        mx = fmaxf(mx, g_asrc[g_csr_src[j] * H + h]);
#pragma unroll
    for (int off = 16; off > 0; off >>= 1)
        mx = fmaxf(mx, __shfl_xor_sync(0xffffffffu, mx, off));
    float m = mx + adv;
    m = (m > 0.f) ? m : 0.2f * m;  // leaky relu commutes with max (monotonic)

    float sum = 0.f;
    for (int j = r0 + lane; j < r1; j += 32) {
        float e = g_asrc[g_csr_src[j] * H + h] + adv;
        e = (e > 0.f) ? e : 0.2f * e;
        float w = __expf(e - m);
        g_walpha[(size_t)j * H + h] = w;
        sum += w;
    }
#pragma unroll
    for (int off = 16; off > 0; off >>= 1)
        sum += __shfl_xor_sync(0xffffffffu, sum, off);
    if (lane == 0) g_adenom[d * H + h] = sum;
}

// ---------------- fused gather + add-skip + LN + ELU + bf16 pack (L1/L2) -----
// One block per dst node, 256 threads, H=4, C=256, LD=1024.
__global__ __launch_bounds__(256) void gat_gather_ln_kernel(
    const float* __restrict__ xl, const float* __restrict__ skip,
    const float* __restrict__ b, const float* __restrict__ skipb,
    const float* __restrict__ g, const float* __restrict__ beta) {
    const int H = 4, C = 256, LD = 1024;
    int d = blockIdx.x;
    int tid = threadIdx.x, lane = tid & 31, wid = tid >> 5;
    int f = tid * 4;
    int r0 = g_row[d], r1 = g_row[d + 1];
    int h0 = f / C;

    // ---- gather (MLP=8) ----
    float4 acc = make_float4(0.f, 0.f, 0.f, 0.f);
    int j = r0;
    for (; j + 7 < r1; j += 8) {
        int s[8];
        float w[8];
        float4 v[8];
#pragma unroll
        for (int q = 0; q < 8; q++) s[q] = g_csr_src[j + q];
#pragma unroll
        for (int q = 0; q < 8; q++) w[q] = g_walpha[(size_t)(j + q) * H + h0];
#pragma unroll
        for (int q = 0; q < 8; q++)
            v[q] = *(reinterpret_cast<const float4*>(xl + (size_t)s[q] * LD) + tid);
#pragma unroll
        for (int q = 0; q < 8; q++) {
            acc.x += w[q] * v[q].x;
            acc.y += w[q] * v[q].y;
            acc.z += w[q] * v[q].z;
            acc.w += w[q] * v[q].w;
        }
    }
    for (; j < r1; j++) {
        int s0 = g_csr_src[j];
        float w0 = g_walpha[(size_t)j * H + h0];
        float4 v0 = *(reinterpret_cast<const float4*>(xl + (size_t)s0 * LD) + tid);
        acc.x += w0 * v0.x;
        acc.y += w0 * v0.y;
        acc.z += w0 * v0.z;
        acc.w += w0 * v0.w;
    }
    float inv = 1.f / (g_adenom[d * H + h0] + 1e-16f);

    // ---- add skip + bias ----
    const size_t base = (size_t)d * 1024;
    float4 s4 = *(const float4*)(skip + base + f);
    float4 b4 = *(const float4*)(b + f);
    float4 sb4 = *(const float4*)(skipb + f);
    float pre[4] = {acc.x * inv + s4.x + b4.x + sb4.x,
                    acc.y * inv + s4.y + b4.y + sb4.y,
                    acc.z * inv + s4.z + b4.z + sb4.z,
                    acc.w * inv + s4.w + b4.w + sb4.w};

    // ---- layernorm (warp-shuffle reductions) ----
    __shared__ float wred[8];
    float sum = pre[0] + pre[1] + pre[2] + pre[3];
#pragma unroll
    for (int off = 16; off > 0; off >>= 1)
        sum += __shfl_xor_sync(0xffffffffu, sum, off);
    if (lane == 0) wred[wid] = sum;
    __syncthreads();
    float mu = (wred[0] + wred[1] + wred[2] + wred[3] +
                wred[4] + wred[5] + wred[6] + wred[7]) * (1.f / 1024.f);
    float sq = 0.f;
#pragma unroll
    for (int k = 0; k < 4; k++) {
        float dlt = pre[k] - mu;
        sq += dlt * dlt;
    }
#pragma unroll
    for (int off = 16; off > 0; off >>= 1)
        sq += __shfl_xor_sync(0xffffffffu, sq, off);
    __syncthreads();   // wred reuse
    if (lane == 0) wred[wid] = sq;
    __syncthreads();
    float rstd = rsqrtf((wred[0] + wred[1] + wred[2] + wred[3] +
                         wred[4] + wred[5] + wred[6] + wred[7]) * (1.f / 1024.f)
                        + 1e-5f);

    // ---- scale/shift + elu + pack ----
    float4 g4 = *(const float4*)(g + f);
    float4 be4 = *(const float4*)(beta + f);
    float y[4];
    y[0] = (pre[0] - mu) * rstd * g4.x + be4.x;
    y[1] = (pre[1] - mu) * rstd * g4.y + be4.y;
    y[2] = (pre[2] - mu) * rstd * g4.z + be4.z;
    y[3] = (pre[3] - mu) * rstd * g4.w + be4.w;
#pragma unroll
    for (int k = 0; k < 4; k++) y[k] = (y[k] > 0.f) ? y[k] : expm1f(y[k]);
    uint32_t hw0, lw0, hw1, lw1;
    packpair(y[0], y[1], hw0, lw0);
    packpair(y[2], y[3], hw1, lw1);
    size_t w = (size_t)d * 512 + 2 * tid;
    g_ah[w] = hw0; g_ah[w + 1] = hw1;
    g_al[w] = lw0; g_al[w + 1] = lw1;
}

// ---------------- layer-3 gather + head-mean fused ---------------------------
__global__ void gat_gather_mean_kernel(const float* __restrict__ xl,
                                       const float* __restrict__ b3,
                                       float* __restrict__ out) {
    const int H = 6, C = 121, HC = 726, LD = 728;
    __shared__ float sv[728];
    int d = blockIdx.x;
    int tid = threadIdx.x;     // 192 threads
    int f = tid * 4;
    int r0 = g_row[d], r1 = g_row[d + 1];

    bool active = (f < HC);
    int h0 = min(f / C, H - 1);
    int h1 = min((f + 1) / C, H - 1);
    int h2 = min((f + 2) / C, H - 1);
    int h3 = min((f + 3) / C, H - 1);

    float4 acc = make_float4(0.f, 0.f, 0.f, 0.f);
    if (active) {
        int j = r0;
        for (; j + 3 < r1; j += 4) {
            int s[4];
            const float* wp[4];
            float4 v[4];
#pragma unroll
            for (int q = 0; q < 4; q++) s[q] = g_csr_src[j + q];
#pragma unroll
            for (int q = 0; q < 4; q++) wp[q] = &g_walpha[(size_t)(j + q) * H];
#pragma unroll
            for (int q = 0; q < 4; q++)
                v[q] = *(reinterpret_cast<const float4*>(xl + (size_t)s[q] * LD) + tid);
#pragma unroll
            for (int q = 0; q < 4; q++) {
                acc.x += wp[q][h0] * v[q].x;
                acc.y += wp[q][h1] * v[q].y;
                acc.z += wp[q][h2] * v[q].z;
                acc.w += wp[q][h3] * v[q].w;
            }
        }
        for (; j < r1; j++) {
            int s0 = g_csr_src[j];
            const float* wp0 = &g_walpha[(size_t)j * H];
            float4 v0 = *(reinterpret_cast<const float4*>(xl + (size_t)s0 * LD) + tid);
            acc.x += wp0[h0] * v0.x;
            acc.y += wp0[h1] * v0.y;
            acc.z += wp0[h2] * v0.z;
            acc.w += wp0[h3] * v0.w;
        }
    }

    const float* dn = &g_adenom[d * H];
    if (active) {
        sv[f]     = acc.x / (dn[h0] + 1e-16f);
        if (f + 1 < HC) sv[f + 1] = acc.y / (dn[h1] + 1e-16f);
        if (f + 2 < HC) sv[f + 2] = acc.z / (dn[h2] + 1e-16f);
        if (f + 3 < HC) sv[f + 3] = acc.w / (dn[h3] + 1e-16f);
    }
    __syncthreads();
    if (tid < C) {
        float s = 0.f;
#pragma unroll
        for (int h = 0; h < 6; h++) s += sv[h * C + tid];
        out[(size_t)d * C + tid] = s * (1.f / 6.f) + b3[tid];
    }
}

// ---------------- host orchestration -----------------------------------------
extern "C" void kernel_launch(void* const* d_in, const int* in_sizes, int n_in,
                              void* d_out, int out_size) {
    const float* x      = (const float*)d_in[0];
    const void*  ei     = d_in[1];
    const float* W1     = (const float*)d_in[2];
    const float* a_src1 = (const float*)d_in[3];
    const float* a_dst1 = (const float*)d_in[4];
    const float* b1     = (const float*)d_in[5];
    const float* W2     = (const float*)d_in[6];
    const float* a_src2 = (const float*)d_in[7];
    const float* a_dst2 = (const float*)d_in[8];
    const float* b2     = (const float*)d_in[9];
    const float* W3     = (const float*)d_in[10];
    const float* a_src3 = (const float*)d_in[11];
    const float* a_dst3 = (const float*)d_in[12];
    const float* b3     = (const float*)d_in[13];
    const float* skipW1 = (const float*)d_in[14];
    const float* skipb1 = (const float*)d_in[15];
    const float* skipW2 = (const float*)d_in[16];
    const float* skipb2 = (const float*)d_in[17];
    const float* g1     = (const float*)d_in[18];
    const float* beta1  = (const float*)d_in[19];
    const float* g2     = (const float*)d_in[20];
    const float* beta2  = (const float*)d_in[21];
    float* out = (float*)d_out;

    float *p_xl, *p_skip;
    uint32_t *p_ah, *p_al, *p_bh, *p_bl;
    cudaGetSymbolAddress((void**)&p_xl, g_xl);
    cudaGetSymbolAddress((void**)&p_skip, g_skip);
    cudaGetSymbolAddress((void**)&p_ah, g_ah);
    cudaGetSymbolAddress((void**)&p_al, g_al);
    cudaGetSymbolAddress((void**)&p_bh, g_bh);
    cudaGetSymbolAddress((void**)&p_bl, g_bl);

    cudaFuncSetAttribute(mma_gemm_async,
                         cudaFuncAttributeMaxDynamicSharedMemorySize,
                         GEMM_SMEM_BYTES);

    // ---- CSR build (edges shared by all 3 layers) ----
    zero_deg_kernel<<<(NN + 255) / 256, 256>>>((const int*)ei);
    build_edges_kernel<<<(NT + 255) / 256, 256>>>(ei);
    scan_kernel<<<1, 1024>>>();
    scatter_kernel<<<(NT + 255) / 256, 256>>>();

    const int gridM = MPAD / 128;   // 157

    // ---- Layer 1: GATConv(50 -> 256, H=4, concat) + skip; K=50 Kpad=64 ----
    {
        const int K = 50, aStride = 32, nkt = 2, Np = 2048;
        cvt_w_kernel<<<((Np * aStride) + 255) / 256, 256>>>(
            W1, 1024, skipW1, 1024, K, Np, aStride, 0);
        cvt_a_kernel<<<((MPAD * aStride) + 255) / 256, 256>>>(
            x, NN, K, aStride, NN * 4);
        mma_gemm_async<<<dim3(16, gridM), 256, GEMM_SMEM_BYTES>>>(
            p_ah, p_al, p_bh, p_bl, p_xl, p_skip, NN, aStride, Np,
            1024, 1024, 1024, 1024, nkt, a_src1, a_dst1, 4, 256);
    }
    edge_softmax_kernel<<<NN, 4 * 32>>>(4);
    gat_gather_ln_kernel<<<NN, 256>>>(p_xl, p_skip, b1, skipb1, g1, beta1);

    // ---- Layer 2: GATConv(1024 -> 256, H=4, concat) + skip ----
    {
        const int aStride = 512, nkt = 32, Np = 2048;
        cvt_w_kernel<<<((Np * aStride) + 255) / 256, 256>>>(
            W2, 1024, skipW2, 1024, 1024, Np, aStride, NN * 4);
        mma_gemm_async<<<dim3(16, gridM), 256, GEMM_SMEM_BYTES>>>(
            p_ah, p_al, p_bh, p_bl, p_xl, p_skip, NN, aStride, Np,
            1024, 1024, 1024, 1024, nkt, a_src2, a_dst2, 4, 256);
    }
    edge_softmax_kernel<<<NN, 4 * 32>>>(4);
    gat_gather_ln_kernel<<<NN, 256>>>(p_xl, p_skip, b2, skipb2, g2, beta2);

    // ---- Layer 3: GATConv(1024 -> 121, H=6, mean); N=726, row stride 728 ----
    {
        const int aStride = 512, nkt = 32, Np = 768;
        cvt_w_kernel<<<((Np * aStride) + 255) / 256, 256>>>(
            W3, 726, (const float*)nullptr, 0, 1024, Np, aStride, 0);
        mma_gemm_async<<<dim3(6, gridM), 256, GEMM_SMEM_BYTES>>>(
            p_ah, p_al, p_bh, p_bl, p_xl, p_xl, NN, aStride, Np,
            726, 728, 0, 728, nkt, nullptr, nullptr, 0, 1);
    }
    compute_alpha_kernel<<<NN, 6 * 32>>>(p_xl, a_src3, a_dst3, 6, 121, 728);
    edge_softmax_kernel<<<NN, 6 * 32>>>(6);
    gat_gather_mean_kernel<<<NN, 192>>>(p_xl, b3, out);
}

// round 17
// speedup vs baseline: 1.0780x; 1.0008x over previous
#include <cuda_runtime.h>
#include <cuda_bf16.h>
#include <cstdint>

#define NN 20000
#define MPAD 20096              // NN rounded up to 128
#define NE 320000
#define NT (NE + NN)

// ---------------- scratch (device globals; no allocations allowed) ----------
__device__ float g_xl[(size_t)NN * 1024];
__device__ float g_skip[(size_t)NN * 1024];
__device__ uint32_t g_ah[(size_t)MPAD * 512];   // packed bf16-hi A plane
__device__ uint32_t g_al[(size_t)MPAD * 512];   // packed bf16-lo A plane
__device__ uint32_t g_bh[(size_t)512 * 2048];   // packed bf16-hi B plane [kp][n]
__device__ uint32_t g_bl[(size_t)512 * 2048];   // packed bf16-lo B plane
__device__ float g_asrc[NN * 6];
__device__ float g_adst[NN * 6];
__device__ float g_walpha[(size_t)NT * 6];      // unnormalized softmax weights (CSR order)
__device__ float g_adenom[NN * 6];
__device__ int   g_deg[NN];
__device__ int   g_row[NN + 1];
__device__ int   g_cursor[NN];
__device__ int   g_csr_src[NT];
__device__ int   g_is64;

// ---------------- zero degrees + edge dtype detection (fused) ----------------
__global__ void zero_deg_kernel(const int* __restrict__ w) {
    int i = blockIdx.x * blockDim.x + threadIdx.x;
    if (i < NN) g_deg[i] = 0;
    if (i == 0) {
        int nz = 0;
        for (int k = 1; k < 2048; k += 2) nz += (w[k] != 0);
        g_is64 = (nz == 0) ? 1 : 0;
    }
}

__device__ __forceinline__ void edge_sd(const void* ei, int t, int& s, int& d) {
    if (t < NE) {
        if (g_is64) {
            const long long* p = (const long long*)ei;
            s = (int)p[t];
            d = (int)p[NE + t];
        } else {
            const int* p = (const int*)ei;
            s = p[t];
            d = p[NE + t];
        }
        s = min(max(s, 0), NN - 1);
        d = min(max(d, 0), NN - 1);
    } else {
        s = d = t - NE;  // self loop
    }
}

__global__ void build_edges_kernel(const void* __restrict__ ei) {
    int t = blockIdx.x * blockDim.x + threadIdx.x;
    if (t >= NT) return;
    int s, d;
    edge_sd(ei, t, s, d);
    atomicAdd(&g_deg[d], 1);
}

// warp-shuffle hierarchical scan
__global__ void scan_kernel() {
    __shared__ int wsum[32];
    __shared__ int carry;
    int tid = threadIdx.x, lane = tid & 31, wid = tid >> 5;
    if (tid == 0) { carry = 0; g_row[0] = 0; }
    __syncthreads();
    for (int base = 0; base < NN; base += 1024) {
        int i = base + tid;
        int v = (i < NN) ? g_deg[i] : 0;
        int val = v;
#pragma unroll
        for (int off = 1; off < 32; off <<= 1) {
            int t = __shfl_up_sync(0xffffffffu, val, off);
            if (lane >= off) val += t;
        }
        if (lane == 31) wsum[wid] = val;
        __syncthreads();
        if (wid == 0) {
            int s = wsum[lane];
#pragma unroll
            for (int off = 1; off < 32; off <<= 1) {
                int t = __shfl_up_sync(0xffffffffu, s, off);
                if (lane >= off) s += t;
            }
            wsum[lane] = s;
        }
        __syncthreads();
        int prefix = carry + (wid > 0 ? wsum[wid - 1] : 0);
        int incl = prefix + val;
        if (i < NN) {
            g_row[i + 1] = incl;
            g_cursor[i]  = incl - v;
        }
        __syncthreads();
        if (tid == 0) carry += wsum[31];
        __syncthreads();
    }
}

__global__ void scatter_kernel(const void* __restrict__ ei) {
    int t = blockIdx.x * blockDim.x + threadIdx.x;
    if (t >= NT) return;
    int s, d;
    edge_sd(ei, t, s, d);
    int pos = atomicAdd(&g_cursor[d], 1);
    g_csr_src[pos] = s;
}

// ============================================================================
// hi/lo bf16 pre-conversion  (zeroAlphaN > 0 -> also zero g_asrc/g_adst[0..N))
// ============================================================================
__device__ __forceinline__ void packpair(float x0, float x1,
                                         uint32_t& hw, uint32_t& lw) {
    uint32_t b0 = __float_as_uint(x0), b1 = __float_as_uint(x1);
    uint32_t h0 = b0 & 0xFFFF0000u, h1 = b1 & 0xFFFF0000u;
    float l0 = x0 - __uint_as_float(h0);
    float l1 = x1 - __uint_as_float(h1);
    __nv_bfloat16 lb0 = __float2bfloat16(l0);
    __nv_bfloat16 lb1 = __float2bfloat16(l1);
    uint16_t u0 = *reinterpret_cast<uint16_t*>(&lb0);
    uint16_t u1 = *reinterpret_cast<uint16_t*>(&lb1);
    hw = (h0 >> 16) | h1;
    lw = (uint32_t)u0 | ((uint32_t)u1 << 16);
}

__global__ void cvt_a_kernel(const float* __restrict__ A, int M, int K,
                             int aStride, int zeroAlphaN) {
    int t = blockIdx.x * blockDim.x + threadIdx.x;
    if (t < zeroAlphaN) { g_asrc[t] = 0.f; g_adst[t] = 0.f; }
    if (t >= MPAD * aStride) return;
    int row = t / aStride, kp = t - row * aStride;
    float x0 = 0.f, x1 = 0.f;
    if (row < M) {
        int k0 = kp * 2;
        const float* ap = &A[(size_t)row * K];
        if (k0 < K)     x0 = ap[k0];
        if (k0 + 1 < K) x1 = ap[k0 + 1];
    }
    uint32_t hw, lw;
    packpair(x0, x1, hw, lw);
    g_ah[t] = hw;
    g_al[t] = lw;
}

__global__ void cvt_w_kernel(const float* __restrict__ B0, int N0c,
                             const float* __restrict__ B1, int N1c,
                             int K, int Np, int kpHalf, int zeroAlphaN) {
    int t = blockIdx.x * blockDim.x + threadIdx.x;
    if (t < zeroAlphaN) { g_asrc[t] = 0.f; g_adst[t] = 0.f; }
    if (t >= kpHalf * Np) return;
    int kp = t / Np, n = t - kp * Np;
    int k0 = kp * 2;
    float x0 = 0.f, x1 = 0.f;
    if (n < N0c) {
        if (k0 < K)     x0 = B0[(size_t)k0 * N0c + n];
        if (k0 + 1 < K) x1 = B0[(size_t)(k0 + 1) * N0c + n];
    } else if (B1 != nullptr && n - N0c < N1c) {
        int nn = n - N0c;
        if (k0 < K)     x0 = B1[(size_t)k0 * N1c + nn];
        if (k0 + 1 < K) x1 = B1[(size_t)(k0 + 1) * N1c + nn];
    }
    uint32_t hw, lw;
    packpair(x0, x1, hw, lw);
    g_bh[t] = hw;
    g_bl[t] = lw;
}

// ============================================================================
// bf16x3 tensor-core GEMM (R11-proven mainloop) + fused alpha epilogue.
// ============================================================================
#define AW  20
#define BW  136
#define A_P_STRIDE (128 * AW)
#define B_P_STRIDE (16 * BW)
#define BUF_WORDS  (2 * A_P_STRIDE + 2 * B_P_STRIDE)
#define GEMM_SMEM_BYTES (2 * BUF_WORDS * 4)

__device__ __forceinline__ void mma_bf16(float* c, const uint32_t* a,
                                         const uint32_t* b) {
    asm volatile(
        "mma.sync.aligned.m16n8k16.row.col.f32.bf16.bf16.f32 "
        "{%0,%1,%2,%3},{%4,%5,%6,%7},{%8,%9},{%0,%1,%2,%3};\n"
        : "+f"(c[0]), "+f"(c[1]), "+f"(c[2]), "+f"(c[3])
        : "r"(a[0]), "r"(a[1]), "r"(a[2]), "r"(a[3]), "r"(b[0]), "r"(b[1]));
}

__device__ __forceinline__ void cp16(uint32_t saddr, const void* g) {
    asm volatile("cp.async.cg.shared.global [%0], [%1], 16;\n"
                 :: "r"(saddr), "l"(g));
}

__global__ __launch_bounds__(256, 2) void mma_gemm_async(
    const uint32_t* __restrict__ Ah, const uint32_t* __restrict__ Al,
    const uint32_t* __restrict__ Bh, const uint32_t* __restrict__ Bl,
    float* __restrict__ C0, float* __restrict__ C1,
    int M, int aStride, int Np, int N0, int ld0, int N1, int ld1, int nkt,
    const float* __restrict__ avec, const float* __restrict__ advec,
    int Halpha, int Calpha) {
    extern __shared__ uint32_t sm[];
    const int tid  = threadIdx.x;
    const int warp = tid >> 5, lane = tid & 31;
    const int group = lane >> 2, tg = lane & 3;
    const int wM = (warp >> 2) * 64;
    const int wN = (warp & 3) * 32;
    const int tileM = blockIdx.y * 128;
    const int tileN = blockIdx.x * 128;

    const int aRow = tid >> 1, aHalf = tid & 1;
    const size_t aGbase = (size_t)(tileM + aRow) * aStride + aHalf * 8;
    const uint32_t aSbase = aRow * AW + aHalf * 8;
    const int bKp = tid >> 4, bN0 = (tid & 15) * 8;
    const uint32_t bSbase = bKp * BW + bN0;

    auto issue = [&](int kt, int buf) {
        uint32_t* s = sm + buf * BUF_WORDS;
        {
            const uint32_t* gh = Ah + aGbase + kt * 16;
            const uint32_t* gl = Al + aGbase + kt * 16;
            uint32_t sh_ = (uint32_t)__cvta_generic_to_shared(s + aSbase);
            uint32_t sl_ = (uint32_t)__cvta_generic_to_shared(s + A_P_STRIDE + aSbase);
            cp16(sh_, gh); cp16(sh_ + 16, gh + 4);
            cp16(sl_, gl); cp16(sl_ + 16, gl + 4);
        }
        {
            const size_t go = (size_t)(kt * 16 + bKp) * Np + tileN + bN0;
            const uint32_t* gh = Bh + go;
            const uint32_t* gl = Bl + go;
            uint32_t* bs = s + 2 * A_P_STRIDE;
            uint32_t sh_ = (uint32_t)__cvta_generic_to_shared(bs + bSbase);
            uint32_t sl_ = (uint32_t)__cvta_generic_to_shared(bs + B_P_STRIDE + bSbase);
            cp16(sh_, gh); cp16(sh_ + 16, gh + 4);
            cp16(sl_, gl); cp16(sl_ + 16, gl + 4);
        }
    };

    float acc[4][4][4] = {};

    issue(0, 0);
    asm volatile("cp.async.commit_group;\n");

    for (int t = 0; t < nkt; t++) {
        const int cur = t & 1;
        const bool more = (t + 1 < nkt);
        if (more) {
            issue(t + 1, cur ^ 1);
            asm volatile("cp.async.commit_group;\n");
            asm volatile("cp.async.wait_group 1;\n");
        } else {
            asm volatile("cp.async.wait_group 0;\n");
        }
        __syncthreads();

        const uint32_t* As_ = sm + cur * BUF_WORDS;
        const uint32_t* Bs_ = sm + cur * BUF_WORDS + 2 * A_P_STRIDE;
#pragma unroll
        for (int ks = 0; ks < 2; ks++) {
            const int kb2 = ks * 8;
            uint32_t afr[4][2][4];
#pragma unroll
            for (int i = 0; i < 4; i++) {
                int row = wM + i * 16 + group;
#pragma unroll
                for (int p = 0; p < 2; p++) {
                    const uint32_t* Ap = As_ + p * A_P_STRIDE;
                    afr[i][p][0] = Ap[row * AW + kb2 + tg];
                    afr[i][p][1] = Ap[(row + 8) * AW + kb2 + tg];
                    afr[i][p][2] = Ap[row * AW + kb2 + 4 + tg];
                    afr[i][p][3] = Ap[(row + 8) * AW + kb2 + 4 + tg];
                }
            }
            uint32_t bfr[4][2][2];
#pragma unroll
            for (int j = 0; j < 4; j++) {
                int n = wN + j * 8 + group;
#pragma unroll
                for (int p = 0; p < 2; p++) {
                    const uint32_t* Bp = Bs_ + p * B_P_STRIDE;
                    bfr[j][p][0] = Bp[(kb2 + tg) * BW + n];
                    bfr[j][p][1] = Bp[(kb2 + 4 + tg) * BW + n];
                }
            }
#pragma unroll
            for (int i = 0; i < 4; i++)
#pragma unroll
                for (int j = 0; j < 4; j++)
                    mma_bf16(acc[i][j], afr[i][0], bfr[j][0]);  // hi*hi
#pragma unroll
            for (int i = 0; i < 4; i++)
#pragma unroll
                for (int j = 0; j < 4; j++)
                    mma_bf16(acc[i][j], afr[i][0], bfr[j][1]);  // hi*lo
#pragma unroll
            for (int i = 0; i < 4; i++)
#pragma unroll
                for (int j = 0; j < 4; j++)
                    mma_bf16(acc[i][j], afr[i][1], bfr[j][0]);  // lo*hi
        }
        __syncthreads();
    }

    auto store = [&](int gm, int gn, float v) {
        if (gm >= M) return;
        if (gn < N0) {
            C0[(size_t)gm * ld0 + gn] = v;
        } else {
            int n2 = gn - N0;
            if (n2 < N1) C1[(size_t)gm * ld1 + n2] = v;
        }
    };
#pragma unroll
    for (int i = 0; i < 4; i++) {
        int row0 = tileM + wM + i * 16 + group;
#pragma unroll
        for (int j = 0; j < 4; j++) {
            int col0 = tileN + wN + j * 8 + tg * 2;
            store(row0,     col0,     acc[i][j][0]);
            store(row0,     col0 + 1, acc[i][j][1]);
            store(row0 + 8, col0,     acc[i][j][2]);
            store(row0 + 8, col0 + 1, acc[i][j][3]);
        }
    }

    if (avec != nullptr && (tileN + wN) < N0) {
        const int head = (tileN + wN) / Calpha;
#pragma unroll
        for (int i = 0; i < 4; i++) {
            float s0s = 0.f, s0d = 0.f, s1s = 0.f, s1d = 0.f;
#pragma unroll
            for (int j = 0; j < 4; j++) {
                int c0 = tileN + wN + j * 8 + tg * 2;
                float av0 = avec[c0], av1 = avec[c0 + 1];
                float ad0 = advec[c0], ad1 = advec[c0 + 1];
                s0s += acc[i][j][0] * av0 + acc[i][j][1] * av1;
                s0d += acc[i][j][0] * ad0 + acc[i][j][1] * ad1;
                s1s += acc[i][j][2] * av0 + acc[i][j][3] * av1;
                s1d += acc[i][j][2] * ad0 + acc[i][j][3] * ad1;
            }
#pragma unroll
            for (int off = 1; off < 4; off <<= 1) {
                s0s += __shfl_xor_sync(0xffffffffu, s0s, off);
                s0d += __shfl_xor_sync(0xffffffffu, s0d, off);
                s1s += __shfl_xor_sync(0xffffffffu, s1s, off);
                s1d += __shfl_xor_sync(0xffffffffu, s1d, off);
            }
            if (tg == 0) {
                int r0 = tileM + wM + i * 16 + group;
                if (r0 < M) {
                    atomicAdd(&g_asrc[r0 * Halpha + head], s0s);
                    atomicAdd(&g_adst[r0 * Halpha + head], s0d);
                }
                if (r0 + 8 < M) {
                    atomicAdd(&g_asrc[(r0 + 8) * Halpha + head], s1s);
                    atomicAdd(&g_adst[(r0 + 8) * Halpha + head], s1d);
                }
            }
        }
    }
}

// ---------------- per-node attention logits (layer 3 only) -------------------
__global__ void compute_alpha_kernel(const float* __restrict__ xl,
                                     const float* __restrict__ a_src,
                                     const float* __restrict__ a_dst,
                                     int H, int C, int LD) {
    int n = blockIdx.x;
    int h = threadIdx.x >> 5;
    int lane = threadIdx.x & 31;
    const float* xr = xl + (size_t)n * LD + h * C;
    float ss = 0.f, sd = 0.f;
    for (int c = lane; c < C; c += 32) {
        float v = xr[c];
        ss += v * a_src[h * C + c];
        sd += v * a_dst[h * C + c];
    }
#pragma unroll
    for (int off = 16; off > 0; off >>= 1) {
        ss += __shfl_down_sync(0xffffffffu, ss, off);
        sd += __shfl_down_sync(0xffffffffu, sd, off);
    }
    if (lane == 0) {
        g_asrc[n * H + h] = ss;
        g_adst[n * H + h] = sd;
    }
}

// ---------------- edge softmax: ONE pass, self-loop logit as shift -----------
// softmax is invariant to any per-(d,h) constant shift; the self-loop edge is
// always present, so m = leakyrelu(asrc[d]+adst[d]) is a valid, well-scaled
// shift (e - m spreads only a few units). Removes the entire max-gather pass.
__global__ void edge_softmax_kernel(int H) {
    int d = blockIdx.x;
    int h = threadIdx.x >> 5;
    int lane = threadIdx.x & 31;
    int r0 = g_row[d], r1 = g_row[d + 1];
    float adv = g_adst[d * H + h];

    float m = g_asrc[d * H + h] + adv;      // self-loop logit
    m = (m > 0.f) ? m : 0.2f * m;

    float sum = 0.f;
    for (int j = r0 + lane; j < r1; j += 32) {
        float e = g_asrc[g_csr_src[j] * H + h] + adv;
        e = (e > 0.f) ? e : 0.2f * e;
        float w = __expf(e - m);
        g_walpha[(size_t)j * H + h] = w;
        sum += w;
    }
#pragma unroll
    for (int off = 16; off > 0; off >>= 1)
        sum += __shfl_xor_sync(0xffffffffu, sum, off);
    if (lane == 0) g_adenom[d * H + h] = sum;
}

// ---------------- fused gather + add-skip + LN + ELU + bf16 pack (L1/L2) -----
__global__ __launch_bounds__(256) void gat_gather_ln_kernel(
    const float* __restrict__ xl, const float* __restrict__ skip,
    const float* __restrict__ b, const float* __restrict__ skipb,
    const float* __restrict__ g, const float* __restrict__ beta) {
    const int H = 4, C = 256, LD = 1024;
    int d = blockIdx.x;
    int tid = threadIdx.x, lane = tid & 31, wid = tid >> 5;
    int f = tid * 4;
    int r0 = g_row[d], r1 = g_row[d + 1];
    int h0 = f / C;

    float4 acc = make_float4(0.f, 0.f, 0.f, 0.f);
    int j = r0;
    for (; j + 7 < r1; j += 8) {
        int s[8];
        float w[8];
        float4 v[8];
#pragma unroll
        for (int q = 0; q < 8; q++) s[q] = g_csr_src[j + q];
#pragma unroll
        for (int q = 0; q < 8; q++) w[q] = g_walpha[(size_t)(j + q) * H + h0];
#pragma unroll
        for (int q = 0; q < 8; q++)
            v[q] = *(reinterpret_cast<const float4*>(xl + (size_t)s[q] * LD) + tid);
#pragma unroll
        for (int q = 0; q < 8; q++) {
            acc.x += w[q] * v[q].x;
            acc.y += w[q] * v[q].y;
            acc.z += w[q] * v[q].z;
            acc.w += w[q] * v[q].w;
        }
    }
    for (; j < r1; j++) {
        int s0 = g_csr_src[j];
        float w0 = g_walpha[(size_t)j * H + h0];
        float4 v0 = *(reinterpret_cast<const float4*>(xl + (size_t)s0 * LD) + tid);
        acc.x += w0 * v0.x;
        acc.y += w0 * v0.y;
        acc.z += w0 * v0.z;
        acc.w += w0 * v0.w;
    }
    float inv = 1.f / (g_adenom[d * H + h0] + 1e-16f);

    const size_t base = (size_t)d * 1024;
    float4 s4 = *(const float4*)(skip + base + f);
    float4 b4 = *(const float4*)(b + f);
    float4 sb4 = *(const float4*)(skipb + f);
    float pre[4] = {acc.x * inv + s4.x + b4.x + sb4.x,
                    acc.y * inv + s4.y + b4.y + sb4.y,
                    acc.z * inv + s4.z + b4.z + sb4.z,
                    acc.w * inv + s4.w + b4.w + sb4.w};

    __shared__ float wred[8];
    float sum = pre[0] + pre[1] + pre[2] + pre[3];
#pragma unroll
    for (int off = 16; off > 0; off >>= 1)
        sum += __shfl_xor_sync(0xffffffffu, sum, off);
    if (lane == 0) wred[wid] = sum;
    __syncthreads();
    float mu = (wred[0] + wred[1] + wred[2] + wred[3] +
                wred[4] + wred[5] + wred[6] + wred[7]) * (1.f / 1024.f);
    float sq = 0.f;
#pragma unroll
    for (int k = 0; k < 4; k++) {
        float dlt = pre[k] - mu;
        sq += dlt * dlt;
    }
#pragma unroll
    for (int off = 16; off > 0; off >>= 1)
        sq += __shfl_xor_sync(0xffffffffu, sq, off);
    __syncthreads();
    if (lane == 0) wred[wid] = sq;
    __syncthreads();
    float rstd = rsqrtf((wred[0] + wred[1] + wred[2] + wred[3] +
                         wred[4] + wred[5] + wred[6] + wred[7]) * (1.f / 1024.f)
                        + 1e-5f);

    float4 g4 = *(const float4*)(g + f);
    float4 be4 = *(const float4*)(beta + f);
    float y[4];
    y[0] = (pre[0] - mu) * rstd * g4.x + be4.x;
    y[1] = (pre[1] - mu) * rstd * g4.y + be4.y;
    y[2] = (pre[2] - mu) * rstd * g4.z + be4.z;
    y[3] = (pre[3] - mu) * rstd * g4.w + be4.w;
#pragma unroll
    for (int k = 0; k < 4; k++) y[k] = (y[k] > 0.f) ? y[k] : expm1f(y[k]);
    uint32_t hw0, lw0, hw1, lw1;
    packpair(y[0], y[1], hw0, lw0);
    packpair(y[2], y[3], hw1, lw1);
    size_t w = (size_t)d * 512 + 2 * tid;
    g_ah[w] = hw0; g_ah[w + 1] = hw1;
    g_al[w] = lw0; g_al[w + 1] = lw1;
}

// ---------------- layer-3 gather + head-mean fused ---------------------------
__global__ void gat_gather_mean_kernel(const float* __restrict__ xl,
                                       const float* __restrict__ b3,
                                       float* __restrict__ out) {
    const int H = 6, C = 121, HC = 726, LD = 728;
    __shared__ float sv[728];
    int d = blockIdx.x;
    int tid = threadIdx.x;     // 192 threads
    int f = tid * 4;
    int r0 = g_row[d], r1 = g_row[d + 1];

    bool active = (f < HC);
    int h0 = min(f / C, H - 1);
    int h1 = min((f + 1) / C, H - 1);
    int h2 = min((f + 2) / C, H - 1);
    int h3 = min((f + 3) / C, H - 1);

    float4 acc = make_float4(0.f, 0.f, 0.f, 0.f);
    if (active) {
        int j = r0;
        for (; j + 3 < r1; j += 4) {
            int s[4];
            const float* wp[4];
            float4 v[4];
#pragma unroll
            for (int q = 0; q < 4; q++) s[q] = g_csr_src[j + q];
#pragma unroll
            for (int q = 0; q < 4; q++) wp[q] = &g_walpha[(size_t)(j + q) * H];
#pragma unroll
            for (int q = 0; q < 4; q++)
                v[q] = *(reinterpret_cast<const float4*>(xl + (size_t)s[q] * LD) + tid);
#pragma unroll
            for (int q = 0; q < 4; q++) {
                acc.x += wp[q][h0] * v[q].x;
                acc.y += wp[q][h1] * v[q].y;
                acc.z += wp[q][h2] * v[q].z;
                acc.w += wp[q][h3] * v[q].w;
            }
        }
        for (; j < r1; j++) {
            int s0 = g_csr_src[j];
            const float* wp0 = &g_walpha[(size_t)j * H];
            float4 v0 = *(reinterpret_cast<const float4*>(xl + (size_t)s0 * LD) + tid);
            acc.x += wp0[h0] * v0.x;
            acc.y += wp0[h1] * v0.y;
            acc.z += wp0[h2] * v0.z;
            acc.w += wp0[h3] * v0.w;
        }
    }

    const float* dn = &g_adenom[d * H];
    if (active) {
        sv[f]     = acc.x / (dn[h0] + 1e-16f);
        if (f + 1 < HC) sv[f + 1] = acc.y / (dn[h1] + 1e-16f);
        if (f + 2 < HC) sv[f + 2] = acc.z / (dn[h2] + 1e-16f);
        if (f + 3 < HC) sv[f + 3] = acc.w / (dn[h3] + 1e-16f);
    }
    __syncthreads();
    if (tid < C) {
        float s = 0.f;
#pragma unroll
        for (int h = 0; h < 6; h++) s += sv[h * C + tid];
        out[(size_t)d * C + tid] = s * (1.f / 6.f) + b3[tid];
    }
}

// ---------------- host orchestration -----------------------------------------
extern "C" void kernel_launch(void* const* d_in, const int* in_sizes, int n_in,
                              void* d_out, int out_size) {
    const float* x      = (const float*)d_in[0];
    const void*  ei     = d_in[1];
    const float* W1     = (const float*)d_in[2];
    const float* a_src1 = (const float*)d_in[3];
    const float* a_dst1 = (const float*)d_in[4];
    const float* b1     = (const float*)d_in[5];
    const float* W2     = (const float*)d_in[6];
    const float* a_src2 = (const float*)d_in[7];
    const float* a_dst2 = (const float*)d_in[8];
    const float* b2     = (const float*)d_in[9];
    const float* W3     = (const float*)d_in[10];
    const float* a_src3 = (const float*)d_in[11];
    const float* a_dst3 = (const float*)d_in[12];
    const float* b3     = (const float*)d_in[13];
    const float* skipW1 = (const float*)d_in[14];
    const float* skipb1 = (const float*)d_in[15];
    const float* skipW2 = (const float*)d_in[16];
    const float* skipb2 = (const float*)d_in[17];
    const float* g1     = (const float*)d_in[18];
    const float* beta1  = (const float*)d_in[19];
    const float* g2     = (const float*)d_in[20];
    const float* beta2  = (const float*)d_in[21];
    float* out = (float*)d_out;

    float *p_xl, *p_skip;
    uint32_t *p_ah, *p_al, *p_bh, *p_bl;
    cudaGetSymbolAddress((void**)&p_xl, g_xl);
    cudaGetSymbolAddress((void**)&p_skip, g_skip);
    cudaGetSymbolAddress((void**)&p_ah, g_ah);
    cudaGetSymbolAddress((void**)&p_al, g_al);
    cudaGetSymbolAddress((void**)&p_bh, g_bh);
    cudaGetSymbolAddress((void**)&p_bl, g_bl);

    cudaFuncSetAttribute(mma_gemm_async,
                         cudaFuncAttributeMaxDynamicSharedMemorySize,
                         GEMM_SMEM_BYTES);

    // ---- CSR build (edges shared by all 3 layers) ----
    zero_deg_kernel<<<(NN + 255) / 256, 256>>>((const int*)ei);
    build_edges_kernel<<<(NT + 255) / 256, 256>>>(ei);
    scan_kernel<<<1, 1024>>>();
    scatter_kernel<<<(NT + 255) / 256, 256>>>(ei);

    const int gridM = MPAD / 128;   // 157

    // ---- Layer 1: GATConv(50 -> 256, H=4, concat) + skip; K=50 Kpad=64 ----
    {
        const int K = 50, aStride = 32, nkt = 2, Np = 2048;
        cvt_w_kernel<<<((Np * aStride) + 255) / 256, 256>>>(
            W1, 1024, skipW1, 1024, K, Np, aStride, 0);
        cvt_a_kernel<<<((MPAD * aStride) + 255) / 256, 256>>>(
            x, NN, K, aStride, NN * 4);
        mma_gemm_async<<<dim3(16, gridM), 256, GEMM_SMEM_BYTES>>>(
            p_ah, p_al, p_bh, p_bl, p_xl, p_skip, NN, aStride, Np,
            1024, 1024, 1024, 1024, nkt, a_src1, a_dst1, 4, 256);
    }
    edge_softmax_kernel<<<NN, 4 * 32>>>(4);
    gat_gather_ln_kernel<<<NN, 256>>>(p_xl, p_skip, b1, skipb1, g1, beta1);

    // ---- Layer 2: GATConv(1024 -> 256, H=4, concat) + skip ----
    {
        const int aStride = 512, nkt = 32, Np = 2048;
        cvt_w_kernel<<<((Np * aStride) + 255) / 256, 256>>>(
            W2, 1024, skipW2, 1024, 1024, Np, aStride, NN * 4);
        mma_gemm_async<<<dim3(16, gridM), 256, GEMM_SMEM_BYTES>>>(
            p_ah, p_al, p_bh, p_bl, p_xl, p_skip, NN, aStride, Np,
            1024, 1024, 1024, 1024, nkt, a_src2, a_dst2, 4, 256);
    }
    edge_softmax_kernel<<<NN, 4 * 32>>>(4);
    gat_gather_ln_kernel<<<NN, 256>>>(p_xl, p_skip, b2, skipb2, g2, beta2);

    // ---- Layer 3: GATConv(1024 -> 121, H=6, mean); N=726, row stride 728 ----
    {
        const int aStride = 512, nkt = 32, Np = 768;
        cvt_w_kernel<<<((Np * aStride) + 255) / 256, 256>>>(
            W3, 726, (const float*)nullptr, 0, 1024, Np, aStride, 0);
        mma_gemm_async<<<dim3(6, gridM), 256, GEMM_SMEM_BYTES>>>(
            p_ah, p_al, p_bh, p_bl, p_xl, p_xl, NN, aStride, Np,
            726, 728, 0, 728, nkt, nullptr, nullptr, 0, 1);
    }
    compute_alpha_kernel<<<NN, 6 * 32>>>(p_xl, a_src3, a_dst3, 6, 121, 728);
    edge_softmax_kernel<<<NN, 6 * 32>>>(6);
    gat_gather_mean_kernel<<<NN, 192>>>(p_xl, b3, out);
}